// round 8
// baseline (speedup 1.0000x reference)
#include <cuda_runtime.h>
#include <math.h>

#define N_NODES  100000
#define N_PAD    100032            // 64-row GEMM tiles: 1563 * 64
#define N_EDGES  1600000
#define IN_DIM   64
#define HIDDEN   128
#define N_GRAPHS 512
#define SCAN_NB  196               // ceil(100000/512)

// ---------------- device scratch (referenced ONLY from device code) ----------------
__device__ __align__(16) int      g_off[N_NODES + 1];
__device__ __align__(16) int      g_cursor[N_NODES];
__device__ __align__(16) int      g_esrc[N_EDGES];
__device__ __align__(16) int      g_bsum[256];
__device__ __align__(16) float    g_bufA[N_PAD * HIDDEN];
__device__ __align__(16) float    g_bufB[N_PAD * HIDDEN];
__device__ __align__(16) float    g_bufC[N_PAD * HIDDEN];
__device__ __align__(16) int      g_start[N_GRAPHS + 1];
__device__            unsigned    g_or;

__device__ __forceinline__ float* bufptr(int i) {
    return (i == 0) ? g_bufA : ((i == 1) ? g_bufB : g_bufC);
}

// f32x2 packed helpers (sm_103a: fma.rn.f32x2 — ptxas never emits this itself)
__device__ __forceinline__ unsigned long long pack2(float a) {
    unsigned long long r;
    asm("mov.b64 %0, {%1, %1};" : "=l"(r) : "f"(a));
    return r;
}
__device__ __forceinline__ void fma2(unsigned long long& d, unsigned long long a, unsigned long long b) {
    asm("fma.rn.f32x2 %0, %1, %2, %0;" : "+l"(d) : "l"(a), "l"(b));
}
__device__ __forceinline__ float2 unpack2(unsigned long long v) {
    float2 f;
    asm("mov.b64 {%0, %1}, %2;" : "=f"(f.x), "=f"(f.y) : "l"(v));
    return f;
}

// mode: 0 = int64 (low word, stride 2), 1 = int32, 2 = float32 bit patterns
__device__ __forceinline__ int dmode() {
    unsigned o = g_or;
    if (o == 0) return 0;
    if (o >= 0x3f000000u) return 2;
    return 1;
}
__device__ __forceinline__ int ld_idx(const unsigned* __restrict__ p, int idx, int mode) {
    if (mode == 0) return (int)p[2 * idx];
    unsigned w = p[idx];
    if (mode == 2) return (int)__uint_as_float(w);
    return (int)w;
}

__global__ void k_detect(const unsigned* __restrict__ ei32) {
    __shared__ unsigned sblk;
    if (threadIdx.x == 0) sblk = 0;
    __syncthreads();
    int e = blockIdx.x * blockDim.x + threadIdx.x;
    unsigned v = ei32[2 * e + 1];
    #pragma unroll
    for (int o = 16; o > 0; o >>= 1) v |= __shfl_xor_sync(0xFFFFFFFFu, v, o);
    if ((threadIdx.x & 31) == 0 && v) atomicOr(&sblk, v);
    __syncthreads();
    if (threadIdx.x == 0 && sblk) atomicOr(&g_or, sblk);
}

__global__ void k_zero_counts() {
    int i = blockIdx.x * blockDim.x + threadIdx.x;
    if (i == 0) g_or = 0;
    if (i <= N_NODES) g_off[i] = 0;
}

__global__ void k_count(const unsigned* __restrict__ ei32) {
    int e = blockIdx.x * blockDim.x + threadIdx.x;
    if (e < N_EDGES) {
        unsigned d = (unsigned)ld_idx(ei32, N_EDGES + e, dmode());
        if (d < N_NODES) atomicAdd(&g_off[d], 1);
    }
}

// ------- 3-phase multi-block scan -------
__global__ void __launch_bounds__(512) k_scan1() {
    __shared__ int sh[512];
    int b = blockIdx.x, t = threadIdx.x;
    int i = b * 512 + t;
    sh[t] = (i < N_NODES) ? g_off[i] : 0;
    __syncthreads();
    for (int o = 256; o > 0; o >>= 1) {
        if (t < o) sh[t] += sh[t + o];
        __syncthreads();
    }
    if (t == 0) g_bsum[b] = sh[0];
}

__global__ void __launch_bounds__(256) k_scan2() {
    __shared__ int sh[256];
    int t = threadIdx.x;
    int v = (t < SCAN_NB) ? g_bsum[t] : 0;
    sh[t] = v;
    __syncthreads();
    for (int off = 1; off < 256; off <<= 1) {
        int u = (t >= off) ? sh[t - off] : 0;
        __syncthreads();
        sh[t] += u;
        __syncthreads();
    }
    if (t < SCAN_NB) g_bsum[t] = sh[t] - v;       // exclusive
    if (t == 255) g_off[N_NODES] = sh[255];       // total
}

__global__ void __launch_bounds__(512) k_scan3() {
    __shared__ int sh[512];
    int b = blockIdx.x, t = threadIdx.x;
    int i = b * 512 + t;
    int v = (i < N_NODES) ? g_off[i] : 0;
    sh[t] = v;
    __syncthreads();
    for (int off = 1; off < 512; off <<= 1) {
        int u = (t >= off) ? sh[t - off] : 0;
        __syncthreads();
        sh[t] += u;
        __syncthreads();
    }
    int excl = sh[t] - v + g_bsum[b];
    if (i < N_NODES) { g_off[i] = excl; g_cursor[i] = excl; }
}

__global__ void k_fill(const unsigned* __restrict__ ei32) {
    int e = blockIdx.x * blockDim.x + threadIdx.x;
    if (e < N_EDGES) {
        int mode = dmode();
        unsigned d = (unsigned)ld_idx(ei32, N_EDGES + e, mode);
        unsigned s = (unsigned)ld_idx(ei32, e, mode);
        if (d < N_NODES && s < N_NODES) {
            int p = atomicAdd(&g_cursor[d], 1);
            g_esrc[p] = (int)s;
        }
    }
}

// agg: out[n] = in[n] + sum_{e: dst==n} in[src_e]   (float4 lanes)
template<int DIM>
__global__ void k_agg(const float* __restrict__ ext, int inb, int outb) {
    const float* in = (inb < 0) ? ext : bufptr(inb);
    float* out = bufptr(outb);
    const int C = DIM / 4;
    int idx = blockIdx.x * blockDim.x + threadIdx.x;
    if (idx >= N_NODES * C) return;
    int node = idx / C;
    int c    = (idx - node * C) * 4;
    float4 acc = *(const float4*)(in + node * DIM + c);
    int s = g_off[node], e = g_off[node + 1];
    for (int i = s; i < e; i++) {
        int src = g_esrc[i];
        float4 v = *(const float4*)(in + src * DIM + c);
        acc.x += v.x; acc.y += v.y; acc.z += v.z; acc.w += v.w;
    }
    *(float4*)(out + node * DIM + c) = acc;
}

// C = relu(A@W + b): 64-row × 128-col tile, 256 threads, f32x2 packed FMA.
// Thread: 4 rows (ty=tid>>4) × 8 cols (tx=tid&15). Tail rows covered by buffer padding.
template<int K>
__global__ void __launch_bounds__(256) k_gemm(int inb,
                                              const float* __restrict__ W,
                                              const float* __restrict__ bias,
                                              int outb) {
    const float* A = bufptr(inb);
    float* Cout = bufptr(outb);
    __shared__ float As[64][K];          // 16KB (K=64) / 32KB (K=128)
    __shared__ float Ws[32][HIDDEN];     // 16KB
    int tid  = threadIdx.x;
    int row0 = blockIdx.x * 64;
    int tx = tid & 15;                   // cols [8tx, 8tx+8)
    int ty = tid >> 4;                   // rows [4ty, 4ty+4)

    for (int i = tid; i < 64 * (K / 4); i += 256) {
        int r = i / (K / 4);
        int c = (i - r * (K / 4)) * 4;
        *(float4*)&As[r][c] = *(const float4*)(A + (row0 + r) * K + c);
    }

    unsigned long long acc[4][4];        // 4 rows × 4 col-pairs
    #pragma unroll
    for (int i = 0; i < 4; i++)
        #pragma unroll
        for (int j = 0; j < 4; j++) acc[i][j] = 0ull;

    for (int kc = 0; kc < K; kc += 32) {
        __syncthreads();
        for (int i = tid; i < 32 * (HIDDEN / 4); i += 256) {
            int r = i / (HIDDEN / 4);
            int c = (i - r * (HIDDEN / 4)) * 4;
            *(float4*)&Ws[r][c] = *(const float4*)(W + (kc + r) * HIDDEN + c);
        }
        __syncthreads();
        #pragma unroll 8
        for (int k2 = 0; k2 < 32; k2++) {
            const unsigned long long* wp = (const unsigned long long*)&Ws[k2][tx * 8];
            unsigned long long w0 = wp[0], w1 = wp[1], w2 = wp[2], w3 = wp[3];
            int k = kc + k2;
            #pragma unroll
            for (int i = 0; i < 4; i++) {
                unsigned long long aa = pack2(As[ty * 4 + i][k]);
                fma2(acc[i][0], aa, w0);
                fma2(acc[i][1], aa, w1);
                fma2(acc[i][2], aa, w2);
                fma2(acc[i][3], aa, w3);
            }
        }
    }

    float4 b0 = *(const float4*)(bias + tx * 8);
    float4 b1 = *(const float4*)(bias + tx * 8 + 4);
    #pragma unroll
    for (int i = 0; i < 4; i++) {
        int row = row0 + ty * 4 + i;
        float2 p0 = unpack2(acc[i][0]);
        float2 p1 = unpack2(acc[i][1]);
        float2 p2 = unpack2(acc[i][2]);
        float2 p3 = unpack2(acc[i][3]);
        float4 o0, o1;
        o0.x = fmaxf(p0.x + b0.x, 0.f); o0.y = fmaxf(p0.y + b0.y, 0.f);
        o0.z = fmaxf(p1.x + b0.z, 0.f); o0.w = fmaxf(p1.y + b0.w, 0.f);
        o1.x = fmaxf(p2.x + b1.x, 0.f); o1.y = fmaxf(p2.y + b1.y, 0.f);
        o1.z = fmaxf(p3.x + b1.z, 0.f); o1.w = fmaxf(p3.y + b1.w, 0.f);
        *(float4*)(Cout + row * HIDDEN + tx * 8)     = o0;
        *(float4*)(Cout + row * HIDDEN + tx * 8 + 4) = o1;
    }
}

__global__ void k_ranges(const unsigned* __restrict__ b32) {
    int g = blockIdx.x * blockDim.x + threadIdx.x;
    if (g > N_GRAPHS) return;
    int mode = dmode();
    int lo = 0, hi = N_NODES;
    while (lo < hi) {
        int mid = (lo + hi) >> 1;
        int bv = ld_idx(b32, mid, mode);
        if (bv < g) lo = mid + 1; else hi = mid;
    }
    g_start[g] = lo;
}

__global__ void __launch_bounds__(128) k_pool(const float* __restrict__ Wc,
                                              const float* __restrict__ bc,
                                              float* __restrict__ out) {
    int g = blockIdx.x;
    int d = threadIdx.x;
    int s = g_start[g], e = g_start[g + 1];
    float acc = 0.f;
    for (int n = s; n < e; n++) acc += g_bufC[n * HIDDEN + d];
    float cnt  = (float)(e - s);
    float mean = acc / fmaxf(cnt, 1.0f);
    float v = mean * Wc[d];

    __shared__ float red[128];
    red[d] = v;
    __syncthreads();
    #pragma unroll
    for (int off = 64; off > 0; off >>= 1) {
        if (d < off) red[d] += red[d + off];
        __syncthreads();
    }
    if (d == 0) out[g] = red[0] + bc[0];
}

// staged diagnostic: overwrites out ONLY on failure
__global__ void __launch_bounds__(256) k_diag(float* __restrict__ out) {
    __shared__ float red[256];
    __shared__ int ok[4];
    int tid = threadIdx.x;
    if (tid == 0) ok[0] = (g_off[N_NODES] == N_EDGES) ? 1 : 0;

    for (int b = 0; b < 3; b++) {
        const float* buf = bufptr(b);
        float s = 0.f;
        for (int i = tid; i < 100000; i += 256) s += fabsf(buf[i]);
        red[tid] = s;
        __syncthreads();
        for (int o = 128; o > 0; o >>= 1) {
            if (tid < o) red[tid] += red[tid + o];
            __syncthreads();
        }
        if (tid == 0) { float t = red[0]; ok[b + 1] = (isfinite(t) && t > 0.f) ? 1 : 0; }
        __syncthreads();
    }

    int m = ok[0] + 2 * ok[1] + 4 * ok[2] + 8 * ok[3];
    if (m == 15) return;
    float V = exp10f((float)(4 + 2 * m));
    for (int g = tid; g < N_GRAPHS; g += 256) out[g] = V;
}

__global__ void k_mark(float* out, float v) {
    int g = blockIdx.x * blockDim.x + threadIdx.x;
    if (g < N_GRAPHS) out[g] = v;
}

// ---------------- launch ----------------
extern "C" void kernel_launch(void* const* d_in, const int* in_sizes, int n_in,
                              void* d_out, int out_size) {
    const float *x, *W1a, *b1a, *W1b, *b1b, *W2a, *b2a, *W2b, *b2b, *Wc, *bc;
    const unsigned *ei, *batch;
    float* out = (float*)d_out;

    if (in_sizes[0] == N_NODES * IN_DIM) {
        x     = (const float*)d_in[0];
        ei    = (const unsigned*)d_in[1];
        batch = (const unsigned*)d_in[2];
        W1a   = (const float*)d_in[3];   b1a = (const float*)d_in[4];
        W1b   = (const float*)d_in[5];   b1b = (const float*)d_in[6];
        W2a   = (const float*)d_in[7];   b2a = (const float*)d_in[8];
        W2b   = (const float*)d_in[9];   b2b = (const float*)d_in[10];
        Wc    = (const float*)d_in[11];  bc  = (const float*)d_in[12];
    } else {
        k_mark<<<2, 256>>>(out, __builtin_nanf(""));
        return;
    }

    // CSR build
    k_zero_counts<<<(N_NODES + 256) / 256, 256>>>();
    k_detect<<<N_EDGES / 256, 256>>>(ei);
    k_count<<<N_EDGES / 256, 256>>>(ei);
    k_scan1<<<SCAN_NB, 512>>>();
    k_scan2<<<1, 256>>>();
    k_scan3<<<SCAN_NB, 512>>>();
    k_fill<<<N_EDGES / 256, 256>>>(ei);

    // conv1
    k_agg<IN_DIM><<<(N_NODES * (IN_DIM / 4)) / 256, 256>>>(x, -1, 0);
    k_gemm<IN_DIM><<<N_PAD / 64, 256>>>(0, W1a, b1a, 1);
    k_gemm<HIDDEN><<<N_PAD / 64, 256>>>(1, W1b, b1b, 2);

    // conv2
    k_agg<HIDDEN><<<(N_NODES * (HIDDEN / 4)) / 256, 256>>>(nullptr, 2, 0);
    k_gemm<HIDDEN><<<N_PAD / 64, 256>>>(0, W2a, b2a, 1);
    k_gemm<HIDDEN><<<N_PAD / 64, 256>>>(1, W2b, b2b, 2);

    // pool + head
    k_ranges<<<3, 256>>>(batch);
    k_pool<<<N_GRAPHS, 128>>>(Wc, bc, out);

    // diagnostic override only on failure
    k_diag<<<1, 256>>>(out);
}

// round 9
// speedup vs baseline: 1.2971x; 1.2971x over previous
#include <cuda_runtime.h>
#include <math.h>

#define N_NODES  100000
#define N_EDGES  1600000
#define IN_DIM   64
#define HIDDEN   128
#define N_GRAPHS 512
#define SCAN_NB  196               // ceil(100000/512)

// ---------------- device scratch (referenced ONLY from device code) ----------------
__device__ __align__(16) int      g_off[N_NODES + 1];
__device__ __align__(16) int      g_cursor[N_NODES];
__device__ __align__(16) int      g_esrc[N_EDGES];
__device__ __align__(16) int      g_bsum[256];
__device__ __align__(16) float    g_bufA[N_NODES * HIDDEN];
__device__ __align__(16) float    g_bufB[N_NODES * HIDDEN];
__device__ __align__(16) float    g_bufC[N_NODES * HIDDEN];
__device__ __align__(16) int      g_start[N_GRAPHS + 1];
__device__            unsigned    g_or;

__device__ __forceinline__ float* bufptr(int i) {
    return (i == 0) ? g_bufA : ((i == 1) ? g_bufB : g_bufC);
}

// mode: 0 = int64 (low word, stride 2), 1 = int32, 2 = float32 bit patterns
__device__ __forceinline__ int dmode() {
    unsigned o = g_or;
    if (o == 0) return 0;
    if (o >= 0x3f000000u) return 2;
    return 1;
}
__device__ __forceinline__ int ld_idx(const unsigned* __restrict__ p, int idx, int mode) {
    if (mode == 0) return (int)p[2 * idx];
    unsigned w = p[idx];
    if (mode == 2) return (int)__uint_as_float(w);
    return (int)w;
}

__global__ void k_detect(const unsigned* __restrict__ ei32) {
    __shared__ unsigned sblk;
    if (threadIdx.x == 0) sblk = 0;
    __syncthreads();
    int e = blockIdx.x * blockDim.x + threadIdx.x;
    unsigned v = ei32[2 * e + 1];
    #pragma unroll
    for (int o = 16; o > 0; o >>= 1) v |= __shfl_xor_sync(0xFFFFFFFFu, v, o);
    if ((threadIdx.x & 31) == 0 && v) atomicOr(&sblk, v);
    __syncthreads();
    if (threadIdx.x == 0 && sblk) atomicOr(&g_or, sblk);
}

__global__ void k_zero_counts() {
    int i = blockIdx.x * blockDim.x + threadIdx.x;
    if (i == 0) g_or = 0;
    if (i <= N_NODES) g_off[i] = 0;
}

__global__ void k_count(const unsigned* __restrict__ ei32) {
    int e = blockIdx.x * blockDim.x + threadIdx.x;
    if (e < N_EDGES) {
        unsigned d = (unsigned)ld_idx(ei32, N_EDGES + e, dmode());
        if (d < N_NODES) atomicAdd(&g_off[d], 1);
    }
}

// ------- 3-phase multi-block scan (measured: phase1 = 4.8us) -------
__global__ void __launch_bounds__(512) k_scan1() {
    __shared__ int sh[512];
    int b = blockIdx.x, t = threadIdx.x;
    int i = b * 512 + t;
    sh[t] = (i < N_NODES) ? g_off[i] : 0;
    __syncthreads();
    for (int o = 256; o > 0; o >>= 1) {
        if (t < o) sh[t] += sh[t + o];
        __syncthreads();
    }
    if (t == 0) g_bsum[b] = sh[0];
}

__global__ void __launch_bounds__(256) k_scan2() {
    __shared__ int sh[256];
    int t = threadIdx.x;
    int v = (t < SCAN_NB) ? g_bsum[t] : 0;
    sh[t] = v;
    __syncthreads();
    for (int off = 1; off < 256; off <<= 1) {
        int u = (t >= off) ? sh[t - off] : 0;
        __syncthreads();
        sh[t] += u;
        __syncthreads();
    }
    if (t < SCAN_NB) g_bsum[t] = sh[t] - v;       // exclusive
    if (t == 255) g_off[N_NODES] = sh[255];       // total
}

__global__ void __launch_bounds__(512) k_scan3() {
    __shared__ int sh[512];
    int b = blockIdx.x, t = threadIdx.x;
    int i = b * 512 + t;
    int v = (i < N_NODES) ? g_off[i] : 0;
    sh[t] = v;
    __syncthreads();
    for (int off = 1; off < 512; off <<= 1) {
        int u = (t >= off) ? sh[t - off] : 0;
        __syncthreads();
        sh[t] += u;
        __syncthreads();
    }
    int excl = sh[t] - v + g_bsum[b];
    if (i < N_NODES) { g_off[i] = excl; g_cursor[i] = excl; }
}

__global__ void k_fill(const unsigned* __restrict__ ei32) {
    int e = blockIdx.x * blockDim.x + threadIdx.x;
    if (e < N_EDGES) {
        int mode = dmode();
        unsigned d = (unsigned)ld_idx(ei32, N_EDGES + e, mode);
        unsigned s = (unsigned)ld_idx(ei32, e, mode);
        if (d < N_NODES && s < N_NODES) {
            int p = atomicAdd(&g_cursor[d], 1);
            g_esrc[p] = (int)s;
        }
    }
}

// agg: out[n] = in[n] + sum_{e: dst==n} in[src_e]   (float4 lanes)
template<int DIM>
__global__ void k_agg(const float* __restrict__ ext, int inb, int outb) {
    const float* in = (inb < 0) ? ext : bufptr(inb);
    float* out = bufptr(outb);
    const int C = DIM / 4;
    int idx = blockIdx.x * blockDim.x + threadIdx.x;
    if (idx >= N_NODES * C) return;
    int node = idx / C;
    int c    = (idx - node * C) * 4;
    float4 acc = *(const float4*)(in + node * DIM + c);
    int s = g_off[node], e = g_off[node + 1];
    for (int i = s; i < e; i++) {
        int src = g_esrc[i];
        float4 v = *(const float4*)(in + src * DIM + c);
        acc.x += v.x; acc.y += v.y; acc.z += v.z; acc.w += v.w;
    }
    *(float4*)(out + node * DIM + c) = acc;
}

// C = relu(A@W + b): 32-row tile, 256 threads, scalar FFMA (measured-good, R7)
template<int K>
__global__ void __launch_bounds__(256) k_gemm(int inb,
                                              const float* __restrict__ W,
                                              const float* __restrict__ bias,
                                              int outb) {
    const float* A = bufptr(inb);
    float* Cout = bufptr(outb);
    __shared__ float As[32][K];
    __shared__ float Ws[32][HIDDEN];
    int tid  = threadIdx.x;
    int row0 = blockIdx.x * 32;

    for (int i = tid; i < 32 * (K / 4); i += 256) {
        int r = i / (K / 4);
        int c = (i - r * (K / 4)) * 4;
        *(float4*)&As[r][c] = *(const float4*)(A + (row0 + r) * K + c);
    }

    float acc[4][4];
    #pragma unroll
    for (int i = 0; i < 4; i++)
        #pragma unroll
        for (int j = 0; j < 4; j++) acc[i][j] = 0.f;

    int tx = tid & 31;
    int ty = tid >> 5;

    for (int kc = 0; kc < K; kc += 32) {
        __syncthreads();
        for (int i = tid; i < 32 * (HIDDEN / 4); i += 256) {
            int r = i / (HIDDEN / 4);
            int c = (i - r * (HIDDEN / 4)) * 4;
            *(float4*)&Ws[r][c] = *(const float4*)(W + (kc + r) * HIDDEN + c);
        }
        __syncthreads();
        #pragma unroll 8
        for (int k2 = 0; k2 < 32; k2++) {
            float4 w = *(float4*)&Ws[k2][tx * 4];
            int k = kc + k2;
            #pragma unroll
            for (int i = 0; i < 4; i++) {
                float a = As[ty * 4 + i][k];
                acc[i][0] += a * w.x;
                acc[i][1] += a * w.y;
                acc[i][2] += a * w.z;
                acc[i][3] += a * w.w;
            }
        }
    }

    float4 bv = *(const float4*)(bias + tx * 4);
    #pragma unroll
    for (int i = 0; i < 4; i++) {
        int row = row0 + ty * 4 + i;
        float4 o;
        o.x = fmaxf(acc[i][0] + bv.x, 0.f);
        o.y = fmaxf(acc[i][1] + bv.y, 0.f);
        o.z = fmaxf(acc[i][2] + bv.z, 0.f);
        o.w = fmaxf(acc[i][3] + bv.w, 0.f);
        *(float4*)(Cout + row * HIDDEN + tx * 4) = o;
    }
}

__global__ void k_ranges(const unsigned* __restrict__ b32) {
    int g = blockIdx.x * blockDim.x + threadIdx.x;
    if (g > N_GRAPHS) return;
    int mode = dmode();
    int lo = 0, hi = N_NODES;
    while (lo < hi) {
        int mid = (lo + hi) >> 1;
        int bv = ld_idx(b32, mid, mode);
        if (bv < g) lo = mid + 1; else hi = mid;
    }
    g_start[g] = lo;
}

__global__ void __launch_bounds__(128) k_pool(const float* __restrict__ Wc,
                                              const float* __restrict__ bc,
                                              float* __restrict__ out) {
    int g = blockIdx.x;
    int d = threadIdx.x;
    int s = g_start[g], e = g_start[g + 1];
    float acc = 0.f;
    for (int n = s; n < e; n++) acc += g_bufC[n * HIDDEN + d];
    float cnt  = (float)(e - s);
    float mean = acc / fmaxf(cnt, 1.0f);
    float v = mean * Wc[d];

    __shared__ float red[128];
    red[d] = v;
    __syncthreads();
    #pragma unroll
    for (int off = 64; off > 0; off >>= 1) {
        if (d < off) red[d] += red[d + off];
        __syncthreads();
    }
    if (d == 0) out[g] = red[0] + bc[0];
}

// staged diagnostic: overwrites out ONLY on failure
__global__ void __launch_bounds__(256) k_diag(float* __restrict__ out) {
    __shared__ float red[256];
    __shared__ int ok[4];
    int tid = threadIdx.x;
    if (tid == 0) ok[0] = (g_off[N_NODES] == N_EDGES) ? 1 : 0;

    for (int b = 0; b < 3; b++) {
        const float* buf = bufptr(b);
        float s = 0.f;
        for (int i = tid; i < 100000; i += 256) s += fabsf(buf[i]);
        red[tid] = s;
        __syncthreads();
        for (int o = 128; o > 0; o >>= 1) {
            if (tid < o) red[tid] += red[tid + o];
            __syncthreads();
        }
        if (tid == 0) { float t = red[0]; ok[b + 1] = (isfinite(t) && t > 0.f) ? 1 : 0; }
        __syncthreads();
    }

    int m = ok[0] + 2 * ok[1] + 4 * ok[2] + 8 * ok[3];
    if (m == 15) return;
    float V = exp10f((float)(4 + 2 * m));
    for (int g = tid; g < N_GRAPHS; g += 256) out[g] = V;
}

__global__ void k_mark(float* out, float v) {
    int g = blockIdx.x * blockDim.x + threadIdx.x;
    if (g < N_GRAPHS) out[g] = v;
}

// ---------------- launch ----------------
extern "C" void kernel_launch(void* const* d_in, const int* in_sizes, int n_in,
                              void* d_out, int out_size) {
    const float *x, *W1a, *b1a, *W1b, *b1b, *W2a, *b2a, *W2b, *b2b, *Wc, *bc;
    const unsigned *ei, *batch;
    float* out = (float*)d_out;

    if (in_sizes[0] == N_NODES * IN_DIM) {
        x     = (const float*)d_in[0];
        ei    = (const unsigned*)d_in[1];
        batch = (const unsigned*)d_in[2];
        W1a   = (const float*)d_in[3];   b1a = (const float*)d_in[4];
        W1b   = (const float*)d_in[5];   b1b = (const float*)d_in[6];
        W2a   = (const float*)d_in[7];   b2a = (const float*)d_in[8];
        W2b   = (const float*)d_in[9];   b2b = (const float*)d_in[10];
        Wc    = (const float*)d_in[11];  bc  = (const float*)d_in[12];
    } else {
        k_mark<<<2, 256>>>(out, __builtin_nanf(""));
        return;
    }

    // CSR build
    k_zero_counts<<<(N_NODES + 256) / 256, 256>>>();
    k_detect<<<N_EDGES / 256, 256>>>(ei);
    k_count<<<N_EDGES / 256, 256>>>(ei);
    k_scan1<<<SCAN_NB, 512>>>();
    k_scan2<<<1, 256>>>();
    k_scan3<<<SCAN_NB, 512>>>();
    k_fill<<<N_EDGES / 256, 256>>>(ei);

    // conv1
    k_agg<IN_DIM><<<(N_NODES * (IN_DIM / 4)) / 256, 256>>>(x, -1, 0);
    k_gemm<IN_DIM><<<N_NODES / 32, 256>>>(0, W1a, b1a, 1);
    k_gemm<HIDDEN><<<N_NODES / 32, 256>>>(1, W1b, b1b, 2);

    // conv2
    k_agg<HIDDEN><<<(N_NODES * (HIDDEN / 4)) / 256, 256>>>(nullptr, 2, 0);
    k_gemm<HIDDEN><<<N_NODES / 32, 256>>>(0, W2a, b2a, 1);
    k_gemm<HIDDEN><<<N_NODES / 32, 256>>>(1, W2b, b2b, 2);

    // pool + head
    k_ranges<<<3, 256>>>(batch);
    k_pool<<<N_GRAPHS, 128>>>(Wc, bc, out);

    // diagnostic override only on failure
    k_diag<<<1, 256>>>(out);
}

// round 11
// speedup vs baseline: 1.3762x; 1.0610x over previous
#include <cuda_runtime.h>
#include <math.h>
#include <stdint.h>

#define N_NODES  100000
#define N_PAD2   100096            // 128-row tiles: 782 * 128
#define N_TILES  782
#define N_EDGES  1600000
#define IN_DIM   64
#define HIDDEN   128
#define N_GRAPHS 512
#define SCAN_NB  196               // ceil(100000/512)

// ---------------- device scratch (referenced ONLY from device code) ----------------
__device__ __align__(16) int      g_off[N_NODES + 1];
__device__ __align__(16) int      g_cursor[N_NODES];
__device__ __align__(16) int      g_esrc[N_EDGES];
__device__ __align__(16) int      g_bsum[256];
__device__ __align__(16) float    g_bufA[N_PAD2 * HIDDEN];
__device__ __align__(16) float    g_bufB[N_PAD2 * HIDDEN];
__device__ __align__(16) float    g_bufC[N_PAD2 * HIDDEN];
__device__ __align__(16) float2   g_WpH[(HIDDEN / 8) * HIDDEN * 4];  // packed W hi
__device__ __align__(16) float2   g_WpL[(HIDDEN / 8) * HIDDEN * 4];  // packed W lo
__device__ __align__(16) int      g_start[N_GRAPHS + 1];
__device__            unsigned    g_or;

__device__ __forceinline__ float* bufptr(int i) {
    return (i == 0) ? g_bufA : ((i == 1) ? g_bufB : g_bufC);
}

__device__ __forceinline__ float tf32f(float a) {
    uint32_t r;
    asm("cvt.rna.tf32.f32 %0, %1;" : "=r"(r) : "f"(a));
    return __uint_as_float(r);
}
__device__ __forceinline__ uint32_t fas(float a) { return __float_as_uint(a); }

// D += A(16x8,row) * B(8x8,col)  — tf32, fp32 accum. Standard sm_80+ PTX.
#define MMA8(c, a, b0, b1)                                                   \
    asm volatile("mma.sync.aligned.m16n8k8.row.col.f32.tf32.tf32.f32 "       \
        "{%0,%1,%2,%3}, {%4,%5,%6,%7}, {%8,%9}, {%0,%1,%2,%3};"              \
        : "+f"((c)[0]), "+f"((c)[1]), "+f"((c)[2]), "+f"((c)[3])             \
        : "r"((a)[0]), "r"((a)[1]), "r"((a)[2]), "r"((a)[3]), "r"(b0), "r"(b1))

// ---------------- index dtype handling ----------------
__device__ __forceinline__ int dmode() {
    unsigned o = g_or;
    if (o == 0) return 0;
    if (o >= 0x3f000000u) return 2;
    return 1;
}
__device__ __forceinline__ int ld_idx(const unsigned* __restrict__ p, int idx, int mode) {
    if (mode == 0) return (int)p[2 * idx];
    unsigned w = p[idx];
    if (mode == 2) return (int)__uint_as_float(w);
    return (int)w;
}

__global__ void k_detect(const unsigned* __restrict__ ei32) {
    __shared__ unsigned sblk;
    if (threadIdx.x == 0) sblk = 0;
    __syncthreads();
    int e = blockIdx.x * blockDim.x + threadIdx.x;
    unsigned v = ei32[2 * e + 1];
    #pragma unroll
    for (int o = 16; o > 0; o >>= 1) v |= __shfl_xor_sync(0xFFFFFFFFu, v, o);
    if ((threadIdx.x & 31) == 0 && v) atomicOr(&sblk, v);
    __syncthreads();
    if (threadIdx.x == 0 && sblk) atomicOr(&g_or, sblk);
}

__global__ void k_zero_counts() {
    int i = blockIdx.x * blockDim.x + threadIdx.x;
    if (i == 0) g_or = 0;
    if (i <= N_NODES) g_off[i] = 0;
}

__global__ void k_count(const unsigned* __restrict__ ei32) {
    int e = blockIdx.x * blockDim.x + threadIdx.x;
    if (e < N_EDGES) {
        unsigned d = (unsigned)ld_idx(ei32, N_EDGES + e, dmode());
        if (d < N_NODES) atomicAdd(&g_off[d], 1);
    }
}

// ------- 3-phase multi-block scan (measured-good) -------
__global__ void __launch_bounds__(512) k_scan1() {
    __shared__ int sh[512];
    int b = blockIdx.x, t = threadIdx.x;
    int i = b * 512 + t;
    sh[t] = (i < N_NODES) ? g_off[i] : 0;
    __syncthreads();
    for (int o = 256; o > 0; o >>= 1) {
        if (t < o) sh[t] += sh[t + o];
        __syncthreads();
    }
    if (t == 0) g_bsum[b] = sh[0];
}

__global__ void __launch_bounds__(256) k_scan2() {
    __shared__ int sh[256];
    int t = threadIdx.x;
    int v = (t < SCAN_NB) ? g_bsum[t] : 0;
    sh[t] = v;
    __syncthreads();
    for (int off = 1; off < 256; off <<= 1) {
        int u = (t >= off) ? sh[t - off] : 0;
        __syncthreads();
        sh[t] += u;
        __syncthreads();
    }
    if (t < SCAN_NB) g_bsum[t] = sh[t] - v;
    if (t == 255) g_off[N_NODES] = sh[255];
}

__global__ void __launch_bounds__(512) k_scan3() {
    __shared__ int sh[512];
    int b = blockIdx.x, t = threadIdx.x;
    int i = b * 512 + t;
    int v = (i < N_NODES) ? g_off[i] : 0;
    sh[t] = v;
    __syncthreads();
    for (int off = 1; off < 512; off <<= 1) {
        int u = (t >= off) ? sh[t - off] : 0;
        __syncthreads();
        sh[t] += u;
        __syncthreads();
    }
    int excl = sh[t] - v + g_bsum[b];
    if (i < N_NODES) { g_off[i] = excl; g_cursor[i] = excl; }
}

__global__ void k_fill(const unsigned* __restrict__ ei32) {
    int e = blockIdx.x * blockDim.x + threadIdx.x;
    if (e < N_EDGES) {
        int mode = dmode();
        unsigned d = (unsigned)ld_idx(ei32, N_EDGES + e, mode);
        unsigned s = (unsigned)ld_idx(ei32, e, mode);
        if (d < N_NODES && s < N_NODES) {
            int p = atomicAdd(&g_cursor[d], 1);
            g_esrc[p] = (int)s;
        }
    }
}

// agg: out[n] = in[n] + sum_{e: dst==n} in[src_e]   (float4 lanes)
template<int DIM>
__global__ void k_agg(const float* __restrict__ ext, int inb, int outb) {
    const float* in = (inb < 0) ? ext : bufptr(inb);
    float* out = bufptr(outb);
    const int C = DIM / 4;
    int idx = blockIdx.x * blockDim.x + threadIdx.x;
    if (idx >= N_NODES * C) return;
    int node = idx / C;
    int c    = (idx - node * C) * 4;
    float4 acc = *(const float4*)(in + node * DIM + c);
    int s = g_off[node], e = g_off[node + 1];
    for (int i = s; i < e; i++) {
        int src = g_esrc[i];
        float4 v = *(const float4*)(in + src * DIM + c);
        acc.x += v.x; acc.y += v.y; acc.z += v.z; acc.w += v.w;
    }
    *(float4*)(out + node * DIM + c) = acc;
}

// prep: pack W[K][128] into mma B-fragment layout, tf32 hi/lo split.
// g_WpH[(k8*128 + n)*4 + j] = {hi(W[k8*8+j][n]), hi(W[k8*8+j+4][n])}
__global__ void k_prepw(const float* __restrict__ W, int K) {
    int idx = blockIdx.x * blockDim.x + threadIdx.x;
    if (idx >= (K / 8) * HIDDEN * 4) return;
    int j  = idx & 3;
    int n  = (idx >> 2) & 127;
    int k8 = idx >> 9;
    float w0 = W[(k8 * 8 + j) * HIDDEN + n];
    float w1 = W[(k8 * 8 + j + 4) * HIDDEN + n];
    float h0 = tf32f(w0), h1 = tf32f(w1);
    g_WpH[idx] = make_float2(h0, h1);
    g_WpL[idx] = make_float2(tf32f(w0 - h0), tf32f(w1 - h1));
}

// ---------------- tensor-core GEMM via legacy mma.sync (tf32, 3-pass split) --------
// Block: 128 rows x 128 cols, 256 threads (8 warps = 4 row-groups x 2 col-halves).
// smem: A hi/lo + B hi/lo, each 16KB, packed [k8][r|n][j] float2 pairs.
#define SMA_H 0
#define SMA_L 16384
#define SMB_H 32768
#define SMB_L 49152
#define SM_TOT 65536

__global__ void __launch_bounds__(256) k_gemm_mma(int inb, const float* __restrict__ bias,
                                                  int outb, int K) {
    extern __shared__ char smem[];
    float2* sAH = (float2*)(smem + SMA_H);
    float2* sAL = (float2*)(smem + SMA_L);
    float2* sBH = (float2*)(smem + SMB_H);
    float2* sBL = (float2*)(smem + SMB_L);
    const float* A = bufptr(inb);
    float* Cout = bufptr(outb);
    int tid  = threadIdx.x;
    int lane = tid & 31, wid = tid >> 5;
    int row0  = blockIdx.x * 128;
    int rbase = (wid & 3) * 32;          // warp's 32 rows
    int nbase = (wid >> 2) * 64;         // warp's 64 cols
    int g = lane >> 2, j = lane & 3;

    float acc[2][8][4];
    #pragma unroll
    for (int mf = 0; mf < 2; mf++)
        #pragma unroll
        for (int nf = 0; nf < 8; nf++)
            #pragma unroll
            for (int c = 0; c < 4; c++) acc[mf][nf][c] = 0.f;

    for (int kc = 0; kc < K; kc += 32) {
        __syncthreads();
        // stage A chunk [128 x 32]: split + pack to fragment layout
        for (int i = tid; i < 2048; i += 256) {
            int r  = i >> 4;
            int k8 = (i >> 2) & 3;
            int jj = i & 3;
            const float* ap = A + (size_t)(row0 + r) * K + kc + k8 * 8 + jj;
            float v0 = ap[0], v1 = ap[4];
            float h0 = tf32f(v0), h1 = tf32f(v1);
            int o = (k8 * 128 + r) * 4 + jj;
            sAH[o] = make_float2(h0, h1);
            sAL[o] = make_float2(tf32f(v0 - h0), tf32f(v1 - h1));
        }
        // stage B chunk: contiguous 16KB copies from pre-packed W
        {
            const float4* gH = (const float4*)(g_WpH + (size_t)kc * 64);
            const float4* gL = (const float4*)(g_WpL + (size_t)kc * 64);
            float4* dH = (float4*)sBH;
            float4* dL = (float4*)sBL;
            for (int i = tid; i < 1024; i += 256) { dH[i] = gH[i]; dL[i] = gL[i]; }
        }
        __syncthreads();

        #pragma unroll
        for (int k8 = 0; k8 < 4; k8++) {
            uint32_t ah[2][4], al[2][4];
            #pragma unroll
            for (int mf = 0; mf < 2; mf++) {
                int r0 = rbase + mf * 16 + g;
                float2 h0 = sAH[(k8 * 128 + r0) * 4 + j];
                float2 h1 = sAH[(k8 * 128 + r0 + 8) * 4 + j];
                float2 l0 = sAL[(k8 * 128 + r0) * 4 + j];
                float2 l1 = sAL[(k8 * 128 + r0 + 8) * 4 + j];
                ah[mf][0] = fas(h0.x); ah[mf][1] = fas(h1.x);
                ah[mf][2] = fas(h0.y); ah[mf][3] = fas(h1.y);
                al[mf][0] = fas(l0.x); al[mf][1] = fas(l1.x);
                al[mf][2] = fas(l0.y); al[mf][3] = fas(l1.y);
            }
            #pragma unroll
            for (int nf = 0; nf < 8; nf++) {
                int n = nbase + nf * 8 + g;
                float2 bh = sBH[(k8 * 128 + n) * 4 + j];
                float2 bl = sBL[(k8 * 128 + n) * 4 + j];
                uint32_t b0h = fas(bh.x), b1h = fas(bh.y);
                uint32_t b0l = fas(bl.x), b1l = fas(bl.y);
                #pragma unroll
                for (int mf = 0; mf < 2; mf++) {
                    MMA8(acc[mf][nf], ah[mf], b0h, b1h);   // hi*hi
                    MMA8(acc[mf][nf], ah[mf], b0l, b1l);   // hi*lo
                    MMA8(acc[mf][nf], al[mf], b0h, b1h);   // lo*hi
                }
            }
        }
    }

    // epilogue: bias + relu, float2 stores
    #pragma unroll
    for (int mf = 0; mf < 2; mf++) {
        int row = row0 + rbase + mf * 16 + g;
        #pragma unroll
        for (int nf = 0; nf < 8; nf++) {
            int col = nbase + nf * 8 + j * 2;
            float2 bv = *(const float2*)(bias + col);
            float2 o0, o1;
            o0.x = fmaxf(acc[mf][nf][0] + bv.x, 0.f);
            o0.y = fmaxf(acc[mf][nf][1] + bv.y, 0.f);
            o1.x = fmaxf(acc[mf][nf][2] + bv.x, 0.f);
            o1.y = fmaxf(acc[mf][nf][3] + bv.y, 0.f);
            *(float2*)(Cout + (size_t)row * HIDDEN + col)       = o0;
            *(float2*)(Cout + (size_t)(row + 8) * HIDDEN + col) = o1;
        }
    }
}

__global__ void k_ranges(const unsigned* __restrict__ b32) {
    int g = blockIdx.x * blockDim.x + threadIdx.x;
    if (g > N_GRAPHS) return;
    int mode = dmode();
    int lo = 0, hi = N_NODES;
    while (lo < hi) {
        int mid = (lo + hi) >> 1;
        int bv = ld_idx(b32, mid, mode);
        if (bv < g) lo = mid + 1; else hi = mid;
    }
    g_start[g] = lo;
}

__global__ void __launch_bounds__(128) k_pool(const float* __restrict__ Wc,
                                              const float* __restrict__ bc,
                                              float* __restrict__ out) {
    int g = blockIdx.x;
    int d = threadIdx.x;
    int s = g_start[g], e = g_start[g + 1];
    float acc = 0.f;
    for (int n = s; n < e; n++) acc += g_bufC[n * HIDDEN + d];
    float cnt  = (float)(e - s);
    float mean = acc / fmaxf(cnt, 1.0f);
    float v = mean * Wc[d];

    __shared__ float red[128];
    red[d] = v;
    __syncthreads();
    #pragma unroll
    for (int off = 64; off > 0; off >>= 1) {
        if (d < off) red[d] += red[d + off];
        __syncthreads();
    }
    if (d == 0) out[g] = red[0] + bc[0];
}

// staged diagnostic: overwrites out ONLY on failure
__global__ void __launch_bounds__(256) k_diag(float* __restrict__ out) {
    __shared__ float red[256];
    __shared__ int ok[4];
    int tid = threadIdx.x;
    if (tid == 0) ok[0] = (g_off[N_NODES] == N_EDGES) ? 1 : 0;

    for (int b = 0; b < 3; b++) {
        const float* buf = bufptr(b);
        float s = 0.f;
        for (int i = tid; i < 100000; i += 256) s += fabsf(buf[i]);
        red[tid] = s;
        __syncthreads();
        for (int o = 128; o > 0; o >>= 1) {
            if (tid < o) red[tid] += red[tid + o];
            __syncthreads();
        }
        if (tid == 0) { float t = red[0]; ok[b + 1] = (isfinite(t) && t > 0.f) ? 1 : 0; }
        __syncthreads();
    }

    int m = ok[0] + 2 * ok[1] + 4 * ok[2] + 8 * ok[3];
    if (m == 15) return;
    float V = exp10f((float)(4 + 2 * m));
    for (int g = tid; g < N_GRAPHS; g += 256) out[g] = V;
}

__global__ void k_mark(float* out, float v) {
    int g = blockIdx.x * blockDim.x + threadIdx.x;
    if (g < N_GRAPHS) out[g] = v;
}

// ---------------- launch ----------------
extern "C" void kernel_launch(void* const* d_in, const int* in_sizes, int n_in,
                              void* d_out, int out_size) {
    const float *x, *W1a, *b1a, *W1b, *b1b, *W2a, *b2a, *W2b, *b2b, *Wc, *bc;
    const unsigned *ei, *batch;
    float* out = (float*)d_out;

    if (in_sizes[0] == N_NODES * IN_DIM) {
        x     = (const float*)d_in[0];
        ei    = (const unsigned*)d_in[1];
        batch = (const unsigned*)d_in[2];
        W1a   = (const float*)d_in[3];   b1a = (const float*)d_in[4];
        W1b   = (const float*)d_in[5];   b1b = (const float*)d_in[6];
        W2a   = (const float*)d_in[7];   b2a = (const float*)d_in[8];
        W2b   = (const float*)d_in[9];   b2b = (const float*)d_in[10];
        Wc    = (const float*)d_in[11];  bc  = (const float*)d_in[12];
    } else {
        k_mark<<<2, 256>>>(out, __builtin_nanf(""));
        return;
    }

    static int smem_set = 0;
    if (!smem_set) {
        cudaFuncSetAttribute(k_gemm_mma, cudaFuncAttributeMaxDynamicSharedMemorySize, SM_TOT);
        smem_set = 1;
    }

    // CSR build
    k_zero_counts<<<(N_NODES + 256) / 256, 256>>>();
    k_detect<<<N_EDGES / 256, 256>>>(ei);
    k_count<<<N_EDGES / 256, 256>>>(ei);
    k_scan1<<<SCAN_NB, 512>>>();
    k_scan2<<<1, 256>>>();
    k_scan3<<<SCAN_NB, 512>>>();
    k_fill<<<N_EDGES / 256, 256>>>(ei);

    // conv1
    k_agg<IN_DIM><<<(N_NODES * (IN_DIM / 4)) / 256, 256>>>(x, -1, 0);
    k_prepw<<<(IN_DIM / 8) * HIDDEN * 4 / 256, 256>>>(W1a, IN_DIM);
    k_gemm_mma<<<N_TILES, 256, SM_TOT>>>(0, b1a, 1, IN_DIM);
    k_prepw<<<(HIDDEN / 8) * HIDDEN * 4 / 256, 256>>>(W1b, HIDDEN);
    k_gemm_mma<<<N_TILES, 256, SM_TOT>>>(1, b1b, 2, HIDDEN);

    // conv2
    k_agg<HIDDEN><<<(N_NODES * (HIDDEN / 4)) / 256, 256>>>(nullptr, 2, 0);
    k_prepw<<<(HIDDEN / 8) * HIDDEN * 4 / 256, 256>>>(W2a, HIDDEN);
    k_gemm_mma<<<N_TILES, 256, SM_TOT>>>(0, b2a, 1, HIDDEN);
    k_prepw<<<(HIDDEN / 8) * HIDDEN * 4 / 256, 256>>>(W2b, HIDDEN);
    k_gemm_mma<<<N_TILES, 256, SM_TOT>>>(1, b2b, 2, HIDDEN);

    // pool + head
    k_ranges<<<3, 256>>>(batch);
    k_pool<<<N_GRAPHS, 128>>>(Wc, bc, out);

    // diagnostic override only on failure
    k_diag<<<1, 256>>>(out);
}

// round 12
// speedup vs baseline: 1.6714x; 1.2145x over previous
#include <cuda_runtime.h>
#include <math.h>
#include <stdint.h>

#define N_NODES  100000
#define N_PAD2   100096            // 128-row tiles: 782 * 128
#define N_TILES  782
#define N_EDGES  1600000
#define IN_DIM   64
#define HIDDEN   128
#define N_GRAPHS 512
#define SCAN_NB  196               // ceil(100000/512)

// ---------------- device scratch (referenced ONLY from device code) ----------------
__device__ __align__(16) int      g_off[N_NODES + 1];
__device__ __align__(16) int      g_cursor[N_NODES];
__device__ __align__(16) int      g_esrc[N_EDGES];
__device__ __align__(16) int      g_bsum[256];
__device__ __align__(16) float    g_bufA[N_PAD2 * HIDDEN];
__device__ __align__(16) float    g_bufB[N_PAD2 * HIDDEN];
__device__ __align__(16) float    g_bufC[N_PAD2 * HIDDEN];
__device__ __align__(16) uint32_t g_WpH[(HIDDEN / 16) * HIDDEN * 8];  // packed bf16x2 W hi
__device__ __align__(16) uint32_t g_WpL[(HIDDEN / 16) * HIDDEN * 8];  // packed bf16x2 W lo
__device__ __align__(16) int      g_start[N_GRAPHS + 1];
__device__            unsigned    g_or;

__device__ __forceinline__ float* bufptr(int i) {
    return (i == 0) ? g_bufA : ((i == 1) ? g_bufB : g_bufC);
}

// pack {lo_half=a, hi_half=b} as bf16x2
__device__ __forceinline__ uint32_t pk_bf2(float a, float b) {
    uint32_t r;
    asm("cvt.rn.bf16x2.f32 %0, %1, %2;" : "=r"(r) : "f"(b), "f"(a));
    return r;
}
__device__ __forceinline__ float bf_lo(uint32_t r) { return __uint_as_float(r << 16); }
__device__ __forceinline__ float bf_hi(uint32_t r) { return __uint_as_float(r & 0xFFFF0000u); }

// D += A(16x16,row) * B(16x8,col) — bf16, fp32 accum. sm_80 baseline PTX.
#define MMA16(c, a, b0, b1)                                                  \
    asm volatile("mma.sync.aligned.m16n8k16.row.col.f32.bf16.bf16.f32 "      \
        "{%0,%1,%2,%3}, {%4,%5,%6,%7}, {%8,%9}, {%0,%1,%2,%3};"              \
        : "+f"((c)[0]), "+f"((c)[1]), "+f"((c)[2]), "+f"((c)[3])             \
        : "r"((a)[0]), "r"((a)[1]), "r"((a)[2]), "r"((a)[3]), "r"(b0), "r"(b1))

// ---------------- index dtype handling ----------------
__device__ __forceinline__ int dmode() {
    unsigned o = g_or;
    if (o == 0) return 0;
    if (o >= 0x3f000000u) return 2;
    return 1;
}
__device__ __forceinline__ int ld_idx(const unsigned* __restrict__ p, int idx, int mode) {
    if (mode == 0) return (int)p[2 * idx];
    unsigned w = p[idx];
    if (mode == 2) return (int)__uint_as_float(w);
    return (int)w;
}

__global__ void k_detect(const unsigned* __restrict__ ei32) {
    __shared__ unsigned sblk;
    if (threadIdx.x == 0) sblk = 0;
    __syncthreads();
    int e = blockIdx.x * blockDim.x + threadIdx.x;
    unsigned v = ei32[2 * e + 1];
    #pragma unroll
    for (int o = 16; o > 0; o >>= 1) v |= __shfl_xor_sync(0xFFFFFFFFu, v, o);
    if ((threadIdx.x & 31) == 0 && v) atomicOr(&sblk, v);
    __syncthreads();
    if (threadIdx.x == 0 && sblk) atomicOr(&g_or, sblk);
}

__global__ void k_zero_counts() {
    int i = blockIdx.x * blockDim.x + threadIdx.x;
    if (i == 0) g_or = 0;
    if (i <= N_NODES) g_off[i] = 0;
}

__global__ void k_count(const unsigned* __restrict__ ei32) {
    int e = blockIdx.x * blockDim.x + threadIdx.x;
    if (e < N_EDGES) {
        unsigned d = (unsigned)ld_idx(ei32, N_EDGES + e, dmode());
        if (d < N_NODES) atomicAdd(&g_off[d], 1);
    }
}

// ------- 3-phase multi-block scan (measured-good) -------
__global__ void __launch_bounds__(512) k_scan1() {
    __shared__ int sh[512];
    int b = blockIdx.x, t = threadIdx.x;
    int i = b * 512 + t;
    sh[t] = (i < N_NODES) ? g_off[i] : 0;
    __syncthreads();
    for (int o = 256; o > 0; o >>= 1) {
        if (t < o) sh[t] += sh[t + o];
        __syncthreads();
    }
    if (t == 0) g_bsum[b] = sh[0];
}

__global__ void __launch_bounds__(256) k_scan2() {
    __shared__ int sh[256];
    int t = threadIdx.x;
    int v = (t < SCAN_NB) ? g_bsum[t] : 0;
    sh[t] = v;
    __syncthreads();
    for (int off = 1; off < 256; off <<= 1) {
        int u = (t >= off) ? sh[t - off] : 0;
        __syncthreads();
        sh[t] += u;
        __syncthreads();
    }
    if (t < SCAN_NB) g_bsum[t] = sh[t] - v;
    if (t == 255) g_off[N_NODES] = sh[255];
}

__global__ void __launch_bounds__(512) k_scan3() {
    __shared__ int sh[512];
    int b = blockIdx.x, t = threadIdx.x;
    int i = b * 512 + t;
    int v = (i < N_NODES) ? g_off[i] : 0;
    sh[t] = v;
    __syncthreads();
    for (int off = 1; off < 512; off <<= 1) {
        int u = (t >= off) ? sh[t - off] : 0;
        __syncthreads();
        sh[t] += u;
        __syncthreads();
    }
    int excl = sh[t] - v + g_bsum[b];
    if (i < N_NODES) { g_off[i] = excl; g_cursor[i] = excl; }
}

__global__ void k_fill(const unsigned* __restrict__ ei32) {
    int e = blockIdx.x * blockDim.x + threadIdx.x;
    if (e < N_EDGES) {
        int mode = dmode();
        unsigned d = (unsigned)ld_idx(ei32, N_EDGES + e, mode);
        unsigned s = (unsigned)ld_idx(ei32, e, mode);
        if (d < N_NODES && s < N_NODES) {
            int p = atomicAdd(&g_cursor[d], 1);
            g_esrc[p] = (int)s;
        }
    }
}

// agg: out[n] = in[n] + sum_{e: dst==n} in[src_e]   (float4 lanes)
template<int DIM>
__global__ void k_agg(const float* __restrict__ ext, int inb, int outb) {
    const float* in = (inb < 0) ? ext : bufptr(inb);
    float* out = bufptr(outb);
    const int C = DIM / 4;
    int idx = blockIdx.x * blockDim.x + threadIdx.x;
    if (idx >= N_NODES * C) return;
    int node = idx / C;
    int c    = (idx - node * C) * 4;
    float4 acc = *(const float4*)(in + node * DIM + c);
    int s = g_off[node], e = g_off[node + 1];
    for (int i = s; i < e; i++) {
        int src = g_esrc[i];
        float4 v = *(const float4*)(in + src * DIM + c);
        acc.x += v.x; acc.y += v.y; acc.z += v.z; acc.w += v.w;
    }
    *(float4*)(out + node * DIM + c) = acc;
}

// prep: pack W[K][128] into bf16x2 B-fragment layout, hi/lo split.
// g_WpH[(kt*128 + n)*8 + jj] = bf16x2{ W[kt*16+2jj][n], W[kt*16+2jj+1][n] }
__global__ void k_prepw(const float* __restrict__ W, int K) {
    int idx = blockIdx.x * blockDim.x + threadIdx.x;
    if (idx >= (K / 16) * HIDDEN * 8) return;
    int jj = idx & 7;
    int n  = (idx >> 3) & 127;
    int kt = idx >> 10;
    float w0 = W[(kt * 16 + 2 * jj) * HIDDEN + n];
    float w1 = W[(kt * 16 + 2 * jj + 1) * HIDDEN + n];
    uint32_t h = pk_bf2(w0, w1);
    uint32_t l = pk_bf2(w0 - bf_lo(h), w1 - bf_hi(h));
    g_WpH[idx] = h;
    g_WpL[idx] = l;
}

// ---------------- tensor-core GEMM: bf16 split, m16n8k16, 3 passes --------
// Block: 128x128 tile, 256 threads (8 warps = 4 row-groups x 2 col-halves).
// Per k-chunk (32): sA/sB each [2 k16-blocks][128][8] bf16x2 = 8KB per array.
__global__ void __launch_bounds__(256) k_gemm_mma(int inb, const float* __restrict__ bias,
                                                  int outb, int K) {
    __shared__ uint32_t sAH[2048], sAL[2048], sBH[2048], sBL[2048];   // 32KB
    const float* A = bufptr(inb);
    float* Cout = bufptr(outb);
    int tid  = threadIdx.x;
    int lane = tid & 31, wid = tid >> 5;
    int row0  = blockIdx.x * 128;
    int rbase = (wid & 3) * 32;          // warp's 32 rows
    int nbase = (wid >> 2) * 64;         // warp's 64 cols
    int g = lane >> 2, j = lane & 3;

    float acc[2][8][4];
    #pragma unroll
    for (int mf = 0; mf < 2; mf++)
        #pragma unroll
        for (int nf = 0; nf < 8; nf++)
            #pragma unroll
            for (int c = 0; c < 4; c++) acc[mf][nf][c] = 0.f;

    for (int kc = 0; kc < K; kc += 32) {
        __syncthreads();
        // stage A chunk [128 x 32] -> split bf16x2 fragment layout
        #pragma unroll
        for (int i = tid; i < 2048; i += 256) {
            int jj = i & 7;
            int r  = (i >> 3) & 127;
            int kb = i >> 10;
            float2 v = *(const float2*)(A + (size_t)(row0 + r) * K + kc + kb * 16 + 2 * jj);
            uint32_t h = pk_bf2(v.x, v.y);
            uint32_t l = pk_bf2(v.x - bf_lo(h), v.y - bf_hi(h));
            sAH[i] = h;
            sAL[i] = l;
        }
        // stage B chunk: contiguous 8KB copies from pre-packed W
        {
            const float4* gH = (const float4*)(g_WpH + (size_t)(kc >> 4) * 1024);
            const float4* gL = (const float4*)(g_WpL + (size_t)(kc >> 4) * 1024);
            #pragma unroll
            for (int i = tid; i < 512; i += 256) {
                ((float4*)sBH)[i] = gH[i];
                ((float4*)sBL)[i] = gL[i];
            }
        }
        __syncthreads();

        #pragma unroll
        for (int kt = 0; kt < 2; kt++) {
            uint32_t ah[2][4], al[2][4];
            #pragma unroll
            for (int mf = 0; mf < 2; mf++) {
                int base = kt * 1024 + (rbase + mf * 16 + g) * 8;
                ah[mf][0] = sAH[base + j];
                ah[mf][1] = sAH[base + 64 + j];
                ah[mf][2] = sAH[base + j + 4];
                ah[mf][3] = sAH[base + 64 + j + 4];
                al[mf][0] = sAL[base + j];
                al[mf][1] = sAL[base + 64 + j];
                al[mf][2] = sAL[base + j + 4];
                al[mf][3] = sAL[base + 64 + j + 4];
            }
            #pragma unroll
            for (int nf = 0; nf < 8; nf++) {
                int bbase = kt * 1024 + (nbase + nf * 8 + g) * 8;
                uint32_t b0h = sBH[bbase + j], b1h = sBH[bbase + j + 4];
                uint32_t b0l = sBL[bbase + j], b1l = sBL[bbase + j + 4];
                #pragma unroll
                for (int mf = 0; mf < 2; mf++) {
                    MMA16(acc[mf][nf], ah[mf], b0h, b1h);   // hi*hi
                    MMA16(acc[mf][nf], ah[mf], b0l, b1l);   // hi*lo
                    MMA16(acc[mf][nf], al[mf], b0h, b1h);   // lo*hi
                }
            }
        }
    }

    // epilogue: bias + relu, float2 stores
    #pragma unroll
    for (int mf = 0; mf < 2; mf++) {
        int row = row0 + rbase + mf * 16 + g;
        #pragma unroll
        for (int nf = 0; nf < 8; nf++) {
            int col = nbase + nf * 8 + j * 2;
            float2 bv = *(const float2*)(bias + col);
            float2 o0, o1;
            o0.x = fmaxf(acc[mf][nf][0] + bv.x, 0.f);
            o0.y = fmaxf(acc[mf][nf][1] + bv.y, 0.f);
            o1.x = fmaxf(acc[mf][nf][2] + bv.x, 0.f);
            o1.y = fmaxf(acc[mf][nf][3] + bv.y, 0.f);
            *(float2*)(Cout + (size_t)row * HIDDEN + col)       = o0;
            *(float2*)(Cout + (size_t)(row + 8) * HIDDEN + col) = o1;
        }
    }
}

__global__ void k_ranges(const unsigned* __restrict__ b32) {
    int g = blockIdx.x * blockDim.x + threadIdx.x;
    if (g > N_GRAPHS) return;
    int mode = dmode();
    int lo = 0, hi = N_NODES;
    while (lo < hi) {
        int mid = (lo + hi) >> 1;
        int bv = ld_idx(b32, mid, mode);
        if (bv < g) lo = mid + 1; else hi = mid;
    }
    g_start[g] = lo;
}

__global__ void __launch_bounds__(128) k_pool(const float* __restrict__ Wc,
                                              const float* __restrict__ bc,
                                              float* __restrict__ out) {
    int g = blockIdx.x;
    int d = threadIdx.x;
    int s = g_start[g], e = g_start[g + 1];
    float acc = 0.f;
    for (int n = s; n < e; n++) acc += g_bufC[n * HIDDEN + d];
    float cnt  = (float)(e - s);
    float mean = acc / fmaxf(cnt, 1.0f);
    float v = mean * Wc[d];

    __shared__ float red[128];
    red[d] = v;
    __syncthreads();
    #pragma unroll
    for (int off = 64; off > 0; off >>= 1) {
        if (d < off) red[d] += red[d + off];
        __syncthreads();
    }
    if (d == 0) out[g] = red[0] + bc[0];
}

// staged diagnostic: overwrites out ONLY on failure
__global__ void __launch_bounds__(256) k_diag(float* __restrict__ out) {
    __shared__ float red[256];
    __shared__ int ok[4];
    int tid = threadIdx.x;
    if (tid == 0) ok[0] = (g_off[N_NODES] == N_EDGES) ? 1 : 0;

    for (int b = 0; b < 3; b++) {
        const float* buf = bufptr(b);
        float s = 0.f;
        for (int i = tid; i < 100000; i += 256) s += fabsf(buf[i]);
        red[tid] = s;
        __syncthreads();
        for (int o = 128; o > 0; o >>= 1) {
            if (tid < o) red[tid] += red[tid + o];
            __syncthreads();
        }
        if (tid == 0) { float t = red[0]; ok[b + 1] = (isfinite(t) && t > 0.f) ? 1 : 0; }
        __syncthreads();
    }

    int m = ok[0] + 2 * ok[1] + 4 * ok[2] + 8 * ok[3];
    if (m == 15) return;
    float V = exp10f((float)(4 + 2 * m));
    for (int g = tid; g < N_GRAPHS; g += 256) out[g] = V;
}

__global__ void k_mark(float* out, float v) {
    int g = blockIdx.x * blockDim.x + threadIdx.x;
    if (g < N_GRAPHS) out[g] = v;
}

// ---------------- launch ----------------
extern "C" void kernel_launch(void* const* d_in, const int* in_sizes, int n_in,
                              void* d_out, int out_size) {
    const float *x, *W1a, *b1a, *W1b, *b1b, *W2a, *b2a, *W2b, *b2b, *Wc, *bc;
    const unsigned *ei, *batch;
    float* out = (float*)d_out;

    if (in_sizes[0] == N_NODES * IN_DIM) {
        x     = (const float*)d_in[0];
        ei    = (const unsigned*)d_in[1];
        batch = (const unsigned*)d_in[2];
        W1a   = (const float*)d_in[3];   b1a = (const float*)d_in[4];
        W1b   = (const float*)d_in[5];   b1b = (const float*)d_in[6];
        W2a   = (const float*)d_in[7];   b2a = (const float*)d_in[8];
        W2b   = (const float*)d_in[9];   b2b = (const float*)d_in[10];
        Wc    = (const float*)d_in[11];  bc  = (const float*)d_in[12];
    } else {
        k_mark<<<2, 256>>>(out, __builtin_nanf(""));
        return;
    }

    // CSR build
    k_zero_counts<<<(N_NODES + 256) / 256, 256>>>();
    k_detect<<<N_EDGES / 256, 256>>>(ei);
    k_count<<<N_EDGES / 256, 256>>>(ei);
    k_scan1<<<SCAN_NB, 512>>>();
    k_scan2<<<1, 256>>>();
    k_scan3<<<SCAN_NB, 512>>>();
    k_fill<<<N_EDGES / 256, 256>>>(ei);

    // conv1
    k_agg<IN_DIM><<<(N_NODES * (IN_DIM / 4)) / 256, 256>>>(x, -1, 0);
    k_prepw<<<(IN_DIM / 16) * HIDDEN * 8 / 256, 256>>>(W1a, IN_DIM);
    k_gemm_mma<<<N_TILES, 256>>>(0, b1a, 1, IN_DIM);
    k_prepw<<<(HIDDEN / 16) * HIDDEN * 8 / 256, 256>>>(W1b, HIDDEN);
    k_gemm_mma<<<N_TILES, 256>>>(1, b1b, 2, HIDDEN);

    // conv2
    k_agg<HIDDEN><<<(N_NODES * (HIDDEN / 4)) / 256, 256>>>(nullptr, 2, 0);
    k_prepw<<<(HIDDEN / 16) * HIDDEN * 8 / 256, 256>>>(W2a, HIDDEN);
    k_gemm_mma<<<N_TILES, 256>>>(0, b2a, 1, HIDDEN);
    k_prepw<<<(HIDDEN / 16) * HIDDEN * 8 / 256, 256>>>(W2b, HIDDEN);
    k_gemm_mma<<<N_TILES, 256>>>(1, b2b, 2, HIDDEN);

    // pool + head
    k_ranges<<<3, 256>>>(batch);
    k_pool<<<N_GRAPHS, 128>>>(Wc, bc, out);

    // diagnostic override only on failure
    k_diag<<<1, 256>>>(out);
}

// round 13
// speedup vs baseline: 2.0864x; 1.2483x over previous
#include <cuda_runtime.h>
#include <math.h>
#include <stdint.h>

#define N_NODES  100000
#define N_PAD2   100096            // 128-row tiles: 782 * 128
#define N_TILES  782
#define N_EDGES  1600000
#define IN_DIM   64
#define HIDDEN   128
#define N_GRAPHS 512
#define SCAN_NB  196               // ceil(100000/512)

// ---------------- device scratch (referenced ONLY from device code) ----------------
__device__ __align__(16) int      g_off[N_NODES + 1];
__device__ __align__(16) int      g_cursor[N_NODES];
__device__ __align__(16) int      g_esrc[N_EDGES];
__device__ __align__(16) int      g_bsum[256];
__device__ __align__(16) float    g_bufC[N_PAD2 * HIDDEN];            // fp32 (agg/pool input)
// A-fragment-layout activations, bf16x2 hi/lo pairs: [kt][row][jj] (kt<=8)
__device__ __align__(16) uint32_t g_AH0[8 * N_PAD2 * 8];
__device__ __align__(16) uint32_t g_AL0[8 * N_PAD2 * 8];
__device__ __align__(16) uint32_t g_AH1[8 * N_PAD2 * 8];
__device__ __align__(16) uint32_t g_AL1[8 * N_PAD2 * 8];
__device__ __align__(16) uint32_t g_WpH[(HIDDEN / 16) * HIDDEN * 8];  // packed bf16x2 W hi
__device__ __align__(16) uint32_t g_WpL[(HIDDEN / 16) * HIDDEN * 8];  // packed bf16x2 W lo
__device__ __align__(16) int      g_start[N_GRAPHS + 1];
__device__            unsigned    g_or;

__device__ __forceinline__ uint32_t* afH(int s) { return s ? g_AH1 : g_AH0; }
__device__ __forceinline__ uint32_t* afL(int s) { return s ? g_AL1 : g_AL0; }

// pack {lo_half=a, hi_half=b} as bf16x2
__device__ __forceinline__ uint32_t pk_bf2(float a, float b) {
    uint32_t r;
    asm("cvt.rn.bf16x2.f32 %0, %1, %2;" : "=r"(r) : "f"(b), "f"(a));
    return r;
}
__device__ __forceinline__ float bf_lo(uint32_t r) { return __uint_as_float(r << 16); }
__device__ __forceinline__ float bf_hi(uint32_t r) { return __uint_as_float(r & 0xFFFF0000u); }

// D += A(16x16,row) * B(16x8,col) — bf16, fp32 accum. sm_80 baseline PTX.
#define MMA16(c, a, b0, b1)                                                  \
    asm volatile("mma.sync.aligned.m16n8k16.row.col.f32.bf16.bf16.f32 "      \
        "{%0,%1,%2,%3}, {%4,%5,%6,%7}, {%8,%9}, {%0,%1,%2,%3};"              \
        : "+f"((c)[0]), "+f"((c)[1]), "+f"((c)[2]), "+f"((c)[3])             \
        : "r"((a)[0]), "r"((a)[1]), "r"((a)[2]), "r"((a)[3]), "r"(b0), "r"(b1))

#define CP16(sm, gp)  asm volatile("cp.async.ca.shared.global [%0], [%1], 16;" :: "r"(sm), "l"(gp) : "memory")
#define CP_COMMIT()   asm volatile("cp.async.commit_group;" ::: "memory")
#define CP_WAIT0()    asm volatile("cp.async.wait_group 0;" ::: "memory")
#define CP_WAIT1()    asm volatile("cp.async.wait_group 1;" ::: "memory")

__device__ __forceinline__ uint32_t smem_u32(const void* p) {
    uint32_t a;
    asm("{ .reg .u64 t; cvta.to.shared.u64 t, %1; cvt.u32.u64 %0, t; }" : "=r"(a) : "l"(p));
    return a;
}

// ---------------- index dtype handling ----------------
__device__ __forceinline__ int dmode() {
    unsigned o = g_or;
    if (o == 0) return 0;
    if (o >= 0x3f000000u) return 2;
    return 1;
}
__device__ __forceinline__ int ld_idx(const unsigned* __restrict__ p, int idx, int mode) {
    if (mode == 0) return (int)p[2 * idx];
    unsigned w = p[idx];
    if (mode == 2) return (int)__uint_as_float(w);
    return (int)w;
}

__global__ void k_detect(const unsigned* __restrict__ ei32) {
    __shared__ unsigned sblk;
    if (threadIdx.x == 0) sblk = 0;
    __syncthreads();
    int e = blockIdx.x * blockDim.x + threadIdx.x;
    unsigned v = ei32[2 * e + 1];
    #pragma unroll
    for (int o = 16; o > 0; o >>= 1) v |= __shfl_xor_sync(0xFFFFFFFFu, v, o);
    if ((threadIdx.x & 31) == 0 && v) atomicOr(&sblk, v);
    __syncthreads();
    if (threadIdx.x == 0 && sblk) atomicOr(&g_or, sblk);
}

__global__ void k_zero_counts() {
    int i = blockIdx.x * blockDim.x + threadIdx.x;
    if (i == 0) g_or = 0;
    if (i <= N_NODES) g_off[i] = 0;
}

__global__ void k_count(const unsigned* __restrict__ ei32) {
    int e = blockIdx.x * blockDim.x + threadIdx.x;
    if (e < N_EDGES) {
        unsigned d = (unsigned)ld_idx(ei32, N_EDGES + e, dmode());
        if (d < N_NODES) atomicAdd(&g_off[d], 1);
    }
}

// ------- 3-phase multi-block scan (measured-good) -------
__global__ void __launch_bounds__(512) k_scan1() {
    __shared__ int sh[512];
    int b = blockIdx.x, t = threadIdx.x;
    int i = b * 512 + t;
    sh[t] = (i < N_NODES) ? g_off[i] : 0;
    __syncthreads();
    for (int o = 256; o > 0; o >>= 1) {
        if (t < o) sh[t] += sh[t + o];
        __syncthreads();
    }
    if (t == 0) g_bsum[b] = sh[0];
}

__global__ void __launch_bounds__(256) k_scan2() {
    __shared__ int sh[256];
    int t = threadIdx.x;
    int v = (t < SCAN_NB) ? g_bsum[t] : 0;
    sh[t] = v;
    __syncthreads();
    for (int off = 1; off < 256; off <<= 1) {
        int u = (t >= off) ? sh[t - off] : 0;
        __syncthreads();
        sh[t] += u;
        __syncthreads();
    }
    if (t < SCAN_NB) g_bsum[t] = sh[t] - v;
    if (t == 255) g_off[N_NODES] = sh[255];
}

__global__ void __launch_bounds__(512) k_scan3() {
    __shared__ int sh[512];
    int b = blockIdx.x, t = threadIdx.x;
    int i = b * 512 + t;
    int v = (i < N_NODES) ? g_off[i] : 0;
    sh[t] = v;
    __syncthreads();
    for (int off = 1; off < 512; off <<= 1) {
        int u = (t >= off) ? sh[t - off] : 0;
        __syncthreads();
        sh[t] += u;
        __syncthreads();
    }
    int excl = sh[t] - v + g_bsum[b];
    if (i < N_NODES) { g_off[i] = excl; g_cursor[i] = excl; }
}

__global__ void k_fill(const unsigned* __restrict__ ei32) {
    int e = blockIdx.x * blockDim.x + threadIdx.x;
    if (e < N_EDGES) {
        int mode = dmode();
        unsigned d = (unsigned)ld_idx(ei32, N_EDGES + e, mode);
        unsigned s = (unsigned)ld_idx(ei32, e, mode);
        if (d < N_NODES && s < N_NODES) {
            int p = atomicAdd(&g_cursor[d], 1);
            g_esrc[p] = (int)s;
        }
    }
}

// agg: acc = in[n] + sum in[src]; emit as bf16x2 hi/lo A-fragment layout into slot 0
template<int DIM>
__global__ void k_agg(const float* __restrict__ ext, int inb) {
    const float* in = (inb < 0) ? ext : g_bufC;
    const int C = DIM / 4;
    int idx = blockIdx.x * blockDim.x + threadIdx.x;
    if (idx >= N_NODES * C) return;
    int node = idx / C;
    int c    = (idx - node * C) * 4;
    float4 acc = *(const float4*)(in + node * DIM + c);
    int s = g_off[node], e = g_off[node + 1];
    for (int i = s; i < e; i++) {
        int src = g_esrc[i];
        float4 v = *(const float4*)(in + src * DIM + c);
        acc.x += v.x; acc.y += v.y; acc.z += v.z; acc.w += v.w;
    }
    uint32_t h0 = pk_bf2(acc.x, acc.y);
    uint32_t h1 = pk_bf2(acc.z, acc.w);
    uint32_t l0 = pk_bf2(acc.x - bf_lo(h0), acc.y - bf_hi(h0));
    uint32_t l1 = pk_bf2(acc.z - bf_lo(h1), acc.w - bf_hi(h1));
    int kt = c >> 4, jj0 = (c & 15) >> 1;
    size_t o = ((size_t)kt * N_PAD2 + node) * 8 + jj0;
    *(uint2*)(g_AH0 + o) = make_uint2(h0, h1);
    *(uint2*)(g_AL0 + o) = make_uint2(l0, l1);
}

// prep: pack W[K][128] into bf16x2 B-fragment layout, hi/lo split.
__global__ void k_prepw(const float* __restrict__ W, int K) {
    int idx = blockIdx.x * blockDim.x + threadIdx.x;
    if (idx >= (K / 16) * HIDDEN * 8) return;
    int jj = idx & 7;
    int n  = (idx >> 3) & 127;
    int kt = idx >> 10;
    float w0 = W[(kt * 16 + 2 * jj) * HIDDEN + n];
    float w1 = W[(kt * 16 + 2 * jj + 1) * HIDDEN + n];
    uint32_t h = pk_bf2(w0, w1);
    uint32_t l = pk_bf2(w0 - bf_lo(h), w1 - bf_hi(h));
    g_WpH[idx] = h;
    g_WpL[idx] = l;
}

// ---------------- pipelined tensor-core GEMM (bf16 split, m16n8k16, 3 passes) ------
// 128x128 tile, 256 threads. 16-k chunks, cp.async double buffer (2x16KB smem).
// in: pre-split fragment layout (slot). out_mode 0: fp32->g_bufC; 1: split->slot1.
__global__ void __launch_bounds__(256) k_gemm_mma(int in_slot, const float* __restrict__ bias,
                                                  int out_mode, int K) {
    __shared__ __align__(16) uint32_t smem[8192];   // 2 stages x 4096 words
    const uint32_t* AH = afH(in_slot);
    const uint32_t* AL = afL(in_slot);
    int tid  = threadIdx.x;
    int lane = tid & 31, wid = tid >> 5;
    int row0  = blockIdx.x * 128;
    int rbase = (wid & 3) * 32;
    int nbase = (wid >> 2) * 64;
    int g = lane >> 2, j = lane & 3;
    uint32_t sb = smem_u32(smem);

    float acc[2][8][4];
    #pragma unroll
    for (int mf = 0; mf < 2; mf++)
        #pragma unroll
        for (int nf = 0; nf < 8; nf++)
            #pragma unroll
            for (int c = 0; c < 4; c++) acc[mf][nf][c] = 0.f;

    int nch = K >> 4;
    // prefetch chunk 0 into stage 0
    {
        size_t aoff = ((size_t)0 * N_PAD2 + row0) * 8 + tid * 4;
        CP16(sb + tid * 16,         AH + aoff);
        CP16(sb + 4096 + tid * 16,  AL + aoff);
        CP16(sb + 8192 + tid * 16,  g_WpH + tid * 4);
        CP16(sb + 12288 + tid * 16, g_WpL + tid * 4);
        CP_COMMIT();
    }
    for (int ch = 0; ch < nch; ch++) {
        if (ch + 1 < nch) {
            uint32_t dst = sb + ((ch + 1) & 1) * 16384;
            size_t aoff = ((size_t)(ch + 1) * N_PAD2 + row0) * 8 + tid * 4;
            size_t boff = (size_t)(ch + 1) * 1024 + tid * 4;
            CP16(dst + tid * 16,         AH + aoff);
            CP16(dst + 4096 + tid * 16,  AL + aoff);
            CP16(dst + 8192 + tid * 16,  g_WpH + boff);
            CP16(dst + 12288 + tid * 16, g_WpL + boff);
            CP_COMMIT();
            CP_WAIT1();
        } else {
            CP_WAIT0();
        }
        __syncthreads();
        const uint32_t* S   = smem + (ch & 1) * 4096;
        const uint32_t* sAH = S;
        const uint32_t* sAL = S + 1024;
        const uint32_t* sBH = S + 2048;
        const uint32_t* sBL = S + 3072;

        uint32_t ah[2][4], al[2][4];
        #pragma unroll
        for (int mf = 0; mf < 2; mf++) {
            int base = (rbase + mf * 16 + g) * 8;
            ah[mf][0] = sAH[base + j];
            ah[mf][1] = sAH[base + 64 + j];
            ah[mf][2] = sAH[base + j + 4];
            ah[mf][3] = sAH[base + 64 + j + 4];
            al[mf][0] = sAL[base + j];
            al[mf][1] = sAL[base + 64 + j];
            al[mf][2] = sAL[base + j + 4];
            al[mf][3] = sAL[base + 64 + j + 4];
        }
        #pragma unroll
        for (int nf = 0; nf < 8; nf++) {
            int bbase = (nbase + nf * 8 + g) * 8;
            uint32_t b0h = sBH[bbase + j], b1h = sBH[bbase + j + 4];
            uint32_t b0l = sBL[bbase + j], b1l = sBL[bbase + j + 4];
            #pragma unroll
            for (int mf = 0; mf < 2; mf++) {
                MMA16(acc[mf][nf], ah[mf], b0h, b1h);   // hi*hi
                MMA16(acc[mf][nf], ah[mf], b0l, b1l);   // hi*lo
                MMA16(acc[mf][nf], al[mf], b0h, b1h);   // lo*hi
            }
        }
        __syncthreads();
    }

    // epilogue: bias + relu; out_mode 0 -> fp32, 1 -> split fragment layout (slot 1)
    #pragma unroll
    for (int mf = 0; mf < 2; mf++) {
        int row = row0 + rbase + mf * 16 + g;
        #pragma unroll
        for (int nf = 0; nf < 8; nf++) {
            int col = nbase + nf * 8 + j * 2;
            float2 bv = *(const float2*)(bias + col);
            float2 o0, o1;
            o0.x = fmaxf(acc[mf][nf][0] + bv.x, 0.f);
            o0.y = fmaxf(acc[mf][nf][1] + bv.y, 0.f);
            o1.x = fmaxf(acc[mf][nf][2] + bv.x, 0.f);
            o1.y = fmaxf(acc[mf][nf][3] + bv.y, 0.f);
            if (out_mode == 0) {
                *(float2*)(g_bufC + (size_t)row * HIDDEN + col)       = o0;
                *(float2*)(g_bufC + (size_t)(row + 8) * HIDDEN + col) = o1;
            } else {
                int kt = col >> 4, jj = (col & 15) >> 1;
                uint32_t h0 = pk_bf2(o0.x, o0.y);
                uint32_t l0 = pk_bf2(o0.x - bf_lo(h0), o0.y - bf_hi(h0));
                uint32_t h1 = pk_bf2(o1.x, o1.y);
                uint32_t l1 = pk_bf2(o1.x - bf_lo(h1), o1.y - bf_hi(h1));
                size_t oa = ((size_t)kt * N_PAD2 + row) * 8 + jj;
                size_t ob = ((size_t)kt * N_PAD2 + row + 8) * 8 + jj;
                g_AH1[oa] = h0; g_AL1[oa] = l0;
                g_AH1[ob] = h1; g_AL1[ob] = l1;
            }
        }
    }
}

__global__ void k_ranges(const unsigned* __restrict__ b32) {
    int g = blockIdx.x * blockDim.x + threadIdx.x;
    if (g > N_GRAPHS) return;
    int mode = dmode();
    int lo = 0, hi = N_NODES;
    while (lo < hi) {
        int mid = (lo + hi) >> 1;
        int bv = ld_idx(b32, mid, mode);
        if (bv < g) lo = mid + 1; else hi = mid;
    }
    g_start[g] = lo;
}

__global__ void __launch_bounds__(128) k_pool(const float* __restrict__ Wc,
                                              const float* __restrict__ bc,
                                              float* __restrict__ out) {
    int g = blockIdx.x;
    int d = threadIdx.x;
    int s = g_start[g], e = g_start[g + 1];
    float acc = 0.f;
    for (int n = s; n < e; n++) acc += g_bufC[(size_t)n * HIDDEN + d];
    float cnt  = (float)(e - s);
    float mean = acc / fmaxf(cnt, 1.0f);
    float v = mean * Wc[d];

    __shared__ float red[128];
    red[d] = v;
    __syncthreads();
    #pragma unroll
    for (int off = 64; off > 0; off >>= 1) {
        if (d < off) red[d] += red[d + off];
        __syncthreads();
    }
    if (d == 0) out[g] = red[0] + bc[0];
}

// staged diagnostic: overwrites out ONLY on failure. m = CSR + 2*bufC
__global__ void __launch_bounds__(256) k_diag(float* __restrict__ out) {
    __shared__ float red[256];
    __shared__ int ok[2];
    int tid = threadIdx.x;
    if (tid == 0) ok[0] = (g_off[N_NODES] == N_EDGES) ? 1 : 0;

    float s = 0.f;
    for (int i = tid; i < 100000; i += 256) s += fabsf(g_bufC[i]);
    red[tid] = s;
    __syncthreads();
    for (int o = 128; o > 0; o >>= 1) {
        if (tid < o) red[tid] += red[tid + o];
        __syncthreads();
    }
    if (tid == 0) { float t = red[0]; ok[1] = (isfinite(t) && t > 0.f) ? 1 : 0; }
    __syncthreads();

    int m = ok[0] + 2 * ok[1];
    if (m == 3) return;
    float V = exp10f((float)(4 + 4 * m));
    for (int g = tid; g < N_GRAPHS; g += 256) out[g] = V;
}

__global__ void k_mark(float* out, float v) {
    int g = blockIdx.x * blockDim.x + threadIdx.x;
    if (g < N_GRAPHS) out[g] = v;
}

// ---------------- launch ----------------
extern "C" void kernel_launch(void* const* d_in, const int* in_sizes, int n_in,
                              void* d_out, int out_size) {
    const float *x, *W1a, *b1a, *W1b, *b1b, *W2a, *b2a, *W2b, *b2b, *Wc, *bc;
    const unsigned *ei, *batch;
    float* out = (float*)d_out;

    if (in_sizes[0] == N_NODES * IN_DIM) {
        x     = (const float*)d_in[0];
        ei    = (const unsigned*)d_in[1];
        batch = (const unsigned*)d_in[2];
        W1a   = (const float*)d_in[3];   b1a = (const float*)d_in[4];
        W1b   = (const float*)d_in[5];   b1b = (const float*)d_in[6];
        W2a   = (const float*)d_in[7];   b2a = (const float*)d_in[8];
        W2b   = (const float*)d_in[9];   b2b = (const float*)d_in[10];
        Wc    = (const float*)d_in[11];  bc  = (const float*)d_in[12];
    } else {
        k_mark<<<2, 256>>>(out, __builtin_nanf(""));
        return;
    }

    // CSR build
    k_zero_counts<<<(N_NODES + 256) / 256, 256>>>();
    k_detect<<<N_EDGES / 256, 256>>>(ei);
    k_count<<<N_EDGES / 256, 256>>>(ei);
    k_scan1<<<SCAN_NB, 512>>>();
    k_scan2<<<1, 256>>>();
    k_scan3<<<SCAN_NB, 512>>>();
    k_fill<<<N_EDGES / 256, 256>>>(ei);

    // conv1: agg -> slot0; GEMM1 -> slot1 (split); GEMM2 -> bufC (fp32)
    k_agg<IN_DIM><<<(N_NODES * (IN_DIM / 4) + 255) / 256, 256>>>(x, -1);
    k_prepw<<<(IN_DIM / 16) * HIDDEN * 8 / 256, 256>>>(W1a, IN_DIM);
    k_gemm_mma<<<N_TILES, 256>>>(0, b1a, 1, IN_DIM);
    k_prepw<<<(HIDDEN / 16) * HIDDEN * 8 / 256, 256>>>(W1b, HIDDEN);
    k_gemm_mma<<<N_TILES, 256>>>(1, b1b, 0, HIDDEN);

    // conv2
    k_agg<HIDDEN><<<(N_NODES * (HIDDEN / 4) + 255) / 256, 256>>>(nullptr, 2);
    k_prepw<<<(HIDDEN / 16) * HIDDEN * 8 / 256, 256>>>(W2a, HIDDEN);
    k_gemm_mma<<<N_TILES, 256>>>(0, b2a, 1, HIDDEN);
    k_prepw<<<(HIDDEN / 16) * HIDDEN * 8 / 256, 256>>>(W2b, HIDDEN);
    k_gemm_mma<<<N_TILES, 256>>>(1, b2b, 0, HIDDEN);

    // pool + head
    k_ranges<<<3, 256>>>(batch);
    k_pool<<<N_GRAPHS, 128>>>(Wc, bc, out);

    // diagnostic override only on failure
    k_diag<<<1, 256>>>(out);
}

// round 14
// speedup vs baseline: 2.4486x; 1.1736x over previous
#include <cuda_runtime.h>
#include <cuda_fp16.h>
#include <math.h>
#include <stdint.h>

#define N_NODES  100000
#define N_PAD2   100096            // 128-row tiles: 782 * 128
#define N_TILES  782
#define N_EDGES  1600000
#define IN_DIM   64
#define HIDDEN   128
#define N_GRAPHS 512
#define SCAN_NB  196               // ceil(100000/512)

// ---------------- device scratch (referenced ONLY from device code) ----------------
__device__ __align__(16) int      g_off[N_NODES + 1];
__device__ __align__(16) int      g_cursor[N_NODES];
__device__ __align__(16) int      g_esrc[N_EDGES];
__device__ __align__(16) int      g_bsum[256];
__device__ __align__(16) float    g_bufC[N_PAD2 * HIDDEN];            // fp32 (agg/pool input)
// A-fragment-layout activations, fp16x2 (hi only): [kt][row][jj] (kt<=8)
__device__ __align__(16) uint32_t g_AH0[8 * N_PAD2 * 8];
__device__ __align__(16) uint32_t g_AH1[8 * N_PAD2 * 8];
__device__ __align__(16) uint32_t g_WpH[(HIDDEN / 16) * HIDDEN * 8];  // packed fp16x2 W hi
__device__ __align__(16) uint32_t g_WpL[(HIDDEN / 16) * HIDDEN * 8];  // packed fp16x2 W lo
__device__ __align__(16) int      g_start[N_GRAPHS + 1];
__device__            unsigned    g_or;

__device__ __forceinline__ uint32_t* afH(int s) { return s ? g_AH1 : g_AH0; }

// pack {lo_half=a, hi_half=b} as fp16x2
__device__ __forceinline__ uint32_t pk_hf2(float a, float b) {
    uint32_t r;
    asm("cvt.rn.f16x2.f32 %0, %1, %2;" : "=r"(r) : "f"(b), "f"(a));
    return r;
}
__device__ __forceinline__ float hf_lo(uint32_t r) {
    return __half2float(__ushort_as_half((unsigned short)(r & 0xFFFFu)));
}
__device__ __forceinline__ float hf_hi(uint32_t r) {
    return __half2float(__ushort_as_half((unsigned short)(r >> 16)));
}

// D += A(16x16,row) * B(16x8,col) — fp16 in, fp32 accum. sm_80 baseline PTX.
#define MMA16(c, a, b0, b1)                                                  \
    asm volatile("mma.sync.aligned.m16n8k16.row.col.f32.f16.f16.f32 "        \
        "{%0,%1,%2,%3}, {%4,%5,%6,%7}, {%8,%9}, {%0,%1,%2,%3};"              \
        : "+f"((c)[0]), "+f"((c)[1]), "+f"((c)[2]), "+f"((c)[3])             \
        : "r"((a)[0]), "r"((a)[1]), "r"((a)[2]), "r"((a)[3]), "r"(b0), "r"(b1))

#define CP16(sm, gp)  asm volatile("cp.async.ca.shared.global [%0], [%1], 16;" :: "r"(sm), "l"(gp) : "memory")
#define CP_COMMIT()   asm volatile("cp.async.commit_group;" ::: "memory")
#define CP_WAIT0()    asm volatile("cp.async.wait_group 0;" ::: "memory")
#define CP_WAIT1()    asm volatile("cp.async.wait_group 1;" ::: "memory")

__device__ __forceinline__ uint32_t smem_u32(const void* p) {
    uint32_t a;
    asm("{ .reg .u64 t; cvta.to.shared.u64 t, %1; cvt.u32.u64 %0, t; }" : "=r"(a) : "l"(p));
    return a;
}

// ---------------- index dtype handling ----------------
__device__ __forceinline__ int dmode() {
    unsigned o = g_or;
    if (o == 0) return 0;
    if (o >= 0x3f000000u) return 2;
    return 1;
}
__device__ __forceinline__ int ld_idx(const unsigned* __restrict__ p, int idx, int mode) {
    if (mode == 0) return (int)p[2 * idx];
    unsigned w = p[idx];
    if (mode == 2) return (int)__uint_as_float(w);
    return (int)w;
}

__global__ void k_detect(const unsigned* __restrict__ ei32) {
    __shared__ unsigned sblk;
    if (threadIdx.x == 0) sblk = 0;
    __syncthreads();
    int e = blockIdx.x * blockDim.x + threadIdx.x;
    unsigned v = ei32[2 * e + 1];
    #pragma unroll
    for (int o = 16; o > 0; o >>= 1) v |= __shfl_xor_sync(0xFFFFFFFFu, v, o);
    if ((threadIdx.x & 31) == 0 && v) atomicOr(&sblk, v);
    __syncthreads();
    if (threadIdx.x == 0 && sblk) atomicOr(&g_or, sblk);
}

__global__ void k_zero_counts() {
    int i = blockIdx.x * blockDim.x + threadIdx.x;
    if (i == 0) g_or = 0;
    if (i <= N_NODES) g_off[i] = 0;
}

__global__ void k_count(const unsigned* __restrict__ ei32) {
    int e = blockIdx.x * blockDim.x + threadIdx.x;
    if (e < N_EDGES) {
        unsigned d = (unsigned)ld_idx(ei32, N_EDGES + e, dmode());
        if (d < N_NODES) atomicAdd(&g_off[d], 1);
    }
}

// ------- 3-phase multi-block scan (measured-good) -------
__global__ void __launch_bounds__(512) k_scan1() {
    __shared__ int sh[512];
    int b = blockIdx.x, t = threadIdx.x;
    int i = b * 512 + t;
    sh[t] = (i < N_NODES) ? g_off[i] : 0;
    __syncthreads();
    for (int o = 256; o > 0; o >>= 1) {
        if (t < o) sh[t] += sh[t + o];
        __syncthreads();
    }
    if (t == 0) g_bsum[b] = sh[0];
}

__global__ void __launch_bounds__(256) k_scan2() {
    __shared__ int sh[256];
    int t = threadIdx.x;
    int v = (t < SCAN_NB) ? g_bsum[t] : 0;
    sh[t] = v;
    __syncthreads();
    for (int off = 1; off < 256; off <<= 1) {
        int u = (t >= off) ? sh[t - off] : 0;
        __syncthreads();
        sh[t] += u;
        __syncthreads();
    }
    if (t < SCAN_NB) g_bsum[t] = sh[t] - v;
    if (t == 255) g_off[N_NODES] = sh[255];
}

__global__ void __launch_bounds__(512) k_scan3() {
    __shared__ int sh[512];
    int b = blockIdx.x, t = threadIdx.x;
    int i = b * 512 + t;
    int v = (i < N_NODES) ? g_off[i] : 0;
    sh[t] = v;
    __syncthreads();
    for (int off = 1; off < 512; off <<= 1) {
        int u = (t >= off) ? sh[t - off] : 0;
        __syncthreads();
        sh[t] += u;
        __syncthreads();
    }
    int excl = sh[t] - v + g_bsum[b];
    if (i < N_NODES) { g_off[i] = excl; g_cursor[i] = excl; }
}

__global__ void k_fill(const unsigned* __restrict__ ei32) {
    int e = blockIdx.x * blockDim.x + threadIdx.x;
    if (e < N_EDGES) {
        int mode = dmode();
        unsigned d = (unsigned)ld_idx(ei32, N_EDGES + e, mode);
        unsigned s = (unsigned)ld_idx(ei32, e, mode);
        if (d < N_NODES && s < N_NODES) {
            int p = atomicAdd(&g_cursor[d], 1);
            g_esrc[p] = (int)s;
        }
    }
}

// agg: acc = in[n] + sum in[src]; emit as fp16x2 A-fragment layout into slot 0
template<int DIM>
__global__ void k_agg(const float* __restrict__ ext, int inb) {
    const float* in = (inb < 0) ? ext : g_bufC;
    const int C = DIM / 4;
    int idx = blockIdx.x * blockDim.x + threadIdx.x;
    if (idx >= N_NODES * C) return;
    int node = idx / C;
    int c    = (idx - node * C) * 4;
    float4 acc = *(const float4*)(in + node * DIM + c);
    int s = g_off[node], e = g_off[node + 1];
    for (int i = s; i < e; i++) {
        int src = g_esrc[i];
        float4 v = *(const float4*)(in + src * DIM + c);
        acc.x += v.x; acc.y += v.y; acc.z += v.z; acc.w += v.w;
    }
    uint32_t h0 = pk_hf2(acc.x, acc.y);
    uint32_t h1 = pk_hf2(acc.z, acc.w);
    int kt = c >> 4, jj0 = (c & 15) >> 1;
    size_t o = ((size_t)kt * N_PAD2 + node) * 8 + jj0;
    *(uint2*)(g_AH0 + o) = make_uint2(h0, h1);
}

// prep: pack W[K][128] into fp16x2 B-fragment layout, hi/lo split.
__global__ void k_prepw(const float* __restrict__ W, int K) {
    int idx = blockIdx.x * blockDim.x + threadIdx.x;
    if (idx >= (K / 16) * HIDDEN * 8) return;
    int jj = idx & 7;
    int n  = (idx >> 3) & 127;
    int kt = idx >> 10;
    float w0 = W[(kt * 16 + 2 * jj) * HIDDEN + n];
    float w1 = W[(kt * 16 + 2 * jj + 1) * HIDDEN + n];
    uint32_t h = pk_hf2(w0, w1);
    uint32_t l = pk_hf2(w0 - hf_lo(h), w1 - hf_hi(h));
    g_WpH[idx] = h;
    g_WpL[idx] = l;
}

// ---------------- pipelined tensor-core GEMM (fp16 split, 2 passes) ------
// 128x128 tile, 256 threads. 16-k chunks, cp.async double buffer (2x12KB smem).
// A hi-only; B hi+lo. out_mode 0: fp32->g_bufC; 1: fp16 frag->slot1.
__global__ void __launch_bounds__(256) k_gemm_mma(int in_slot, const float* __restrict__ bias,
                                                  int out_mode, int K) {
    __shared__ __align__(16) uint32_t smem[6144];   // 2 stages x 3072 words (12KB)
    const uint32_t* AH = afH(in_slot);
    int tid  = threadIdx.x;
    int lane = tid & 31, wid = tid >> 5;
    int row0  = blockIdx.x * 128;
    int rbase = (wid & 3) * 32;
    int nbase = (wid >> 2) * 64;
    int g = lane >> 2, j = lane & 3;
    uint32_t sb = smem_u32(smem);

    float acc[2][8][4];
    #pragma unroll
    for (int mf = 0; mf < 2; mf++)
        #pragma unroll
        for (int nf = 0; nf < 8; nf++)
            #pragma unroll
            for (int c = 0; c < 4; c++) acc[mf][nf][c] = 0.f;

    int nch = K >> 4;
    // prefetch chunk 0 into stage 0
    {
        size_t aoff = ((size_t)0 * N_PAD2 + row0) * 8 + tid * 4;
        CP16(sb + tid * 16,        AH + aoff);
        CP16(sb + 4096 + tid * 16, g_WpH + tid * 4);
        CP16(sb + 8192 + tid * 16, g_WpL + tid * 4);
        CP_COMMIT();
    }
    for (int ch = 0; ch < nch; ch++) {
        if (ch + 1 < nch) {
            uint32_t dst = sb + ((ch + 1) & 1) * 12288;
            size_t aoff = ((size_t)(ch + 1) * N_PAD2 + row0) * 8 + tid * 4;
            size_t boff = (size_t)(ch + 1) * 1024 + tid * 4;
            CP16(dst + tid * 16,        AH + aoff);
            CP16(dst + 4096 + tid * 16, g_WpH + boff);
            CP16(dst + 8192 + tid * 16, g_WpL + boff);
            CP_COMMIT();
            CP_WAIT1();
        } else {
            CP_WAIT0();
        }
        __syncthreads();
        const uint32_t* S   = smem + (ch & 1) * 3072;
        const uint32_t* sAH = S;
        const uint32_t* sBH = S + 1024;
        const uint32_t* sBL = S + 2048;

        uint32_t ah[2][4];
        #pragma unroll
        for (int mf = 0; mf < 2; mf++) {
            int base = (rbase + mf * 16 + g) * 8;
            ah[mf][0] = sAH[base + j];
            ah[mf][1] = sAH[base + 64 + j];
            ah[mf][2] = sAH[base + j + 4];
            ah[mf][3] = sAH[base + 64 + j + 4];
        }
        #pragma unroll
        for (int nf = 0; nf < 8; nf++) {
            int bbase = (nbase + nf * 8 + g) * 8;
            uint32_t b0h = sBH[bbase + j], b1h = sBH[bbase + j + 4];
            uint32_t b0l = sBL[bbase + j], b1l = sBL[bbase + j + 4];
            #pragma unroll
            for (int mf = 0; mf < 2; mf++) {
                MMA16(acc[mf][nf], ah[mf], b0h, b1h);   // hi*hi
                MMA16(acc[mf][nf], ah[mf], b0l, b1l);   // hi*lo
            }
        }
        __syncthreads();
    }

    // epilogue: bias + relu; out_mode 0 -> fp32, 1 -> fp16 frag layout (slot 1)
    #pragma unroll
    for (int mf = 0; mf < 2; mf++) {
        int row = row0 + rbase + mf * 16 + g;
        #pragma unroll
        for (int nf = 0; nf < 8; nf++) {
            int col = nbase + nf * 8 + j * 2;
            float2 bv = *(const float2*)(bias + col);
            float2 o0, o1;
            o0.x = fmaxf(acc[mf][nf][0] + bv.x, 0.f);
            o0.y = fmaxf(acc[mf][nf][1] + bv.y, 0.f);
            o1.x = fmaxf(acc[mf][nf][2] + bv.x, 0.f);
            o1.y = fmaxf(acc[mf][nf][3] + bv.y, 0.f);
            if (out_mode == 0) {
                *(float2*)(g_bufC + (size_t)row * HIDDEN + col)       = o0;
                *(float2*)(g_bufC + (size_t)(row + 8) * HIDDEN + col) = o1;
            } else {
                int kt = col >> 4, jj = (col & 15) >> 1;
                size_t oa = ((size_t)kt * N_PAD2 + row) * 8 + jj;
                size_t ob = ((size_t)kt * N_PAD2 + row + 8) * 8 + jj;
                g_AH1[oa] = pk_hf2(o0.x, o0.y);
                g_AH1[ob] = pk_hf2(o1.x, o1.y);
            }
        }
    }
}

__global__ void k_ranges(const unsigned* __restrict__ b32) {
    int g = blockIdx.x * blockDim.x + threadIdx.x;
    if (g > N_GRAPHS) return;
    int mode = dmode();
    int lo = 0, hi = N_NODES;
    while (lo < hi) {
        int mid = (lo + hi) >> 1;
        int bv = ld_idx(b32, mid, mode);
        if (bv < g) lo = mid + 1; else hi = mid;
    }
    g_start[g] = lo;
}

__global__ void __launch_bounds__(128) k_pool(const float* __restrict__ Wc,
                                              const float* __restrict__ bc,
                                              float* __restrict__ out) {
    int g = blockIdx.x;
    int d = threadIdx.x;
    int s = g_start[g], e = g_start[g + 1];
    float acc = 0.f;
    for (int n = s; n < e; n++) acc += g_bufC[(size_t)n * HIDDEN + d];
    float cnt  = (float)(e - s);
    float mean = acc / fmaxf(cnt, 1.0f);
    float v = mean * Wc[d];

    __shared__ float red[128];
    red[d] = v;
    __syncthreads();
    #pragma unroll
    for (int off = 64; off > 0; off >>= 1) {
        if (d < off) red[d] += red[d + off];
        __syncthreads();
    }
    if (d == 0) out[g] = red[0] + bc[0];
}

// staged diagnostic: overwrites out ONLY on failure. m = CSR + 2*bufC
__global__ void __launch_bounds__(256) k_diag(float* __restrict__ out) {
    __shared__ float red[256];
    __shared__ int ok[2];
    int tid = threadIdx.x;
    if (tid == 0) ok[0] = (g_off[N_NODES] == N_EDGES) ? 1 : 0;

    float s = 0.f;
    for (int i = tid; i < 100000; i += 256) s += fabsf(g_bufC[i]);
    red[tid] = s;
    __syncthreads();
    for (int o = 128; o > 0; o >>= 1) {
        if (tid < o) red[tid] += red[tid + o];
        __syncthreads();
    }
    if (tid == 0) { float t = red[0]; ok[1] = (isfinite(t) && t > 0.f) ? 1 : 0; }
    __syncthreads();

    int m = ok[0] + 2 * ok[1];
    if (m == 3) return;
    float V = exp10f((float)(4 + 4 * m));
    for (int g = tid; g < N_GRAPHS; g += 256) out[g] = V;
}

__global__ void k_mark(float* out, float v) {
    int g = blockIdx.x * blockDim.x + threadIdx.x;
    if (g < N_GRAPHS) out[g] = v;
}

// ---------------- launch ----------------
extern "C" void kernel_launch(void* const* d_in, const int* in_sizes, int n_in,
                              void* d_out, int out_size) {
    const float *x, *W1a, *b1a, *W1b, *b1b, *W2a, *b2a, *W2b, *b2b, *Wc, *bc;
    const unsigned *ei, *batch;
    float* out = (float*)d_out;

    if (in_sizes[0] == N_NODES * IN_DIM) {
        x     = (const float*)d_in[0];
        ei    = (const unsigned*)d_in[1];
        batch = (const unsigned*)d_in[2];
        W1a   = (const float*)d_in[3];   b1a = (const float*)d_in[4];
        W1b   = (const float*)d_in[5];   b1b = (const float*)d_in[6];
        W2a   = (const float*)d_in[7];   b2a = (const float*)d_in[8];
        W2b   = (const float*)d_in[9];   b2b = (const float*)d_in[10];
        Wc    = (const float*)d_in[11];  bc  = (const float*)d_in[12];
    } else {
        k_mark<<<2, 256>>>(out, __builtin_nanf(""));
        return;
    }

    // CSR build
    k_zero_counts<<<(N_NODES + 256) / 256, 256>>>();
    k_detect<<<N_EDGES / 256, 256>>>(ei);
    k_count<<<N_EDGES / 256, 256>>>(ei);
    k_scan1<<<SCAN_NB, 512>>>();
    k_scan2<<<1, 256>>>();
    k_scan3<<<SCAN_NB, 512>>>();
    k_fill<<<N_EDGES / 256, 256>>>(ei);

    // conv1: agg -> slot0; GEMM1 -> slot1 (fp16 frag); GEMM2 -> bufC (fp32)
    k_agg<IN_DIM><<<(N_NODES * (IN_DIM / 4) + 255) / 256, 256>>>(x, -1);
    k_prepw<<<(IN_DIM / 16) * HIDDEN * 8 / 256, 256>>>(W1a, IN_DIM);
    k_gemm_mma<<<N_TILES, 256>>>(0, b1a, 1, IN_DIM);
    k_prepw<<<(HIDDEN / 16) * HIDDEN * 8 / 256, 256>>>(W1b, HIDDEN);
    k_gemm_mma<<<N_TILES, 256>>>(1, b1b, 0, HIDDEN);

    // conv2
    k_agg<HIDDEN><<<(N_NODES * (HIDDEN / 4) + 255) / 256, 256>>>(nullptr, 2);
    k_prepw<<<(HIDDEN / 16) * HIDDEN * 8 / 256, 256>>>(W2a, HIDDEN);
    k_gemm_mma<<<N_TILES, 256>>>(0, b2a, 1, HIDDEN);
    k_prepw<<<(HIDDEN / 16) * HIDDEN * 8 / 256, 256>>>(W2b, HIDDEN);
    k_gemm_mma<<<N_TILES, 256>>>(1, b2b, 0, HIDDEN);

    // pool + head
    k_ranges<<<3, 256>>>(batch);
    k_pool<<<N_GRAPHS, 128>>>(Wc, bc, out);

    // diagnostic override only on failure
    k_diag<<<1, 256>>>(out);
}

// round 15
// speedup vs baseline: 2.5637x; 1.0470x over previous
#include <cuda_runtime.h>
#include <cuda_fp16.h>
#include <math.h>
#include <stdint.h>

#define N_NODES  100000
#define N_PAD2   100096            // 128-row tiles: 782 * 128
#define N_TILES  782
#define N_EDGES  1600000
#define IN_DIM   64
#define HIDDEN   128
#define N_GRAPHS 512
#define SCAN_NB  196               // ceil(100000/512)

// ---------------- device scratch (referenced ONLY from device code) ----------------
__device__ __align__(16) int      g_off[N_NODES + 1];
__device__ __align__(16) int      g_cursor[N_NODES];
__device__ __align__(16) int      g_esrc[N_EDGES];
__device__ __align__(16) int      g_bsum[256];
__device__ __align__(16) float    g_bufC[N_PAD2 * HIDDEN];            // fp32 (pool input)
__device__ __align__(16) uint32_t g_x16[N_NODES * (IN_DIM / 2)];      // x as fp16x2 linear
__device__ __align__(16) uint32_t g_h16[N_PAD2 * (HIDDEN / 2)];       // h1 as fp16x2 linear
// A-fragment-layout activations, fp16x2 (hi only): [kt][row][jj] (kt<=8)
__device__ __align__(16) uint32_t g_AH0[8 * N_PAD2 * 8];
__device__ __align__(16) uint32_t g_AH1[8 * N_PAD2 * 8];
__device__ __align__(16) uint32_t g_WpH[(HIDDEN / 16) * HIDDEN * 8];  // packed fp16x2 W hi
__device__ __align__(16) uint32_t g_WpL[(HIDDEN / 16) * HIDDEN * 8];  // packed fp16x2 W lo
__device__ __align__(16) int      g_start[N_GRAPHS + 1];
__device__            unsigned    g_or;

__device__ __forceinline__ uint32_t* afH(int s) { return s ? g_AH1 : g_AH0; }

// pack {lo_half=a, hi_half=b} as fp16x2
__device__ __forceinline__ uint32_t pk_hf2(float a, float b) {
    uint32_t r;
    asm("cvt.rn.f16x2.f32 %0, %1, %2;" : "=r"(r) : "f"(b), "f"(a));
    return r;
}
__device__ __forceinline__ float hf_lo(uint32_t r) {
    return __half2float(__ushort_as_half((unsigned short)(r & 0xFFFFu)));
}
__device__ __forceinline__ float hf_hi(uint32_t r) {
    return __half2float(__ushort_as_half((unsigned short)(r >> 16)));
}
__device__ __forceinline__ float2 up2(uint32_t w) {
    __half2 h = *(__half2*)&w;
    return __half22float2(h);
}

// D += A(16x16,row) * B(16x8,col) — fp16 in, fp32 accum. sm_80 baseline PTX.
#define MMA16(c, a, b0, b1)                                                  \
    asm volatile("mma.sync.aligned.m16n8k16.row.col.f32.f16.f16.f32 "        \
        "{%0,%1,%2,%3}, {%4,%5,%6,%7}, {%8,%9}, {%0,%1,%2,%3};"              \
        : "+f"((c)[0]), "+f"((c)[1]), "+f"((c)[2]), "+f"((c)[3])             \
        : "r"((a)[0]), "r"((a)[1]), "r"((a)[2]), "r"((a)[3]), "r"(b0), "r"(b1))

#define CP16(sm, gp)  asm volatile("cp.async.ca.shared.global [%0], [%1], 16;" :: "r"(sm), "l"(gp) : "memory")
#define CP_COMMIT()   asm volatile("cp.async.commit_group;" ::: "memory")
#define CP_WAIT0()    asm volatile("cp.async.wait_group 0;" ::: "memory")
#define CP_WAIT1()    asm volatile("cp.async.wait_group 1;" ::: "memory")

__device__ __forceinline__ uint32_t smem_u32(const void* p) {
    uint32_t a;
    asm("{ .reg .u64 t; cvta.to.shared.u64 t, %1; cvt.u32.u64 %0, t; }" : "=r"(a) : "l"(p));
    return a;
}

// ---------------- index dtype handling ----------------
__device__ __forceinline__ int dmode() {
    unsigned o = g_or;
    if (o == 0) return 0;
    if (o >= 0x3f000000u) return 2;
    return 1;
}
__device__ __forceinline__ int ld_idx(const unsigned* __restrict__ p, int idx, int mode) {
    if (mode == 0) return (int)p[2 * idx];
    unsigned w = p[idx];
    if (mode == 2) return (int)__uint_as_float(w);
    return (int)w;
}

__global__ void k_detect(const unsigned* __restrict__ ei32) {
    __shared__ unsigned sblk;
    if (threadIdx.x == 0) sblk = 0;
    __syncthreads();
    int e = blockIdx.x * blockDim.x + threadIdx.x;
    unsigned v = ei32[2 * e + 1];
    #pragma unroll
    for (int o = 16; o > 0; o >>= 1) v |= __shfl_xor_sync(0xFFFFFFFFu, v, o);
    if ((threadIdx.x & 31) == 0 && v) atomicOr(&sblk, v);
    __syncthreads();
    if (threadIdx.x == 0 && sblk) atomicOr(&g_or, sblk);
}

__global__ void k_zero_counts() {
    int i = blockIdx.x * blockDim.x + threadIdx.x;
    if (i == 0) g_or = 0;
    if (i <= N_NODES) g_off[i] = 0;
}

__global__ void k_count(const unsigned* __restrict__ ei32) {
    int e = blockIdx.x * blockDim.x + threadIdx.x;
    if (e < N_EDGES) {
        unsigned d = (unsigned)ld_idx(ei32, N_EDGES + e, dmode());
        if (d < N_NODES) atomicAdd(&g_off[d], 1);
    }
}

// ------- 3-phase multi-block scan (measured-good) -------
__global__ void __launch_bounds__(512) k_scan1() {
    __shared__ int sh[512];
    int b = blockIdx.x, t = threadIdx.x;
    int i = b * 512 + t;
    sh[t] = (i < N_NODES) ? g_off[i] : 0;
    __syncthreads();
    for (int o = 256; o > 0; o >>= 1) {
        if (t < o) sh[t] += sh[t + o];
        __syncthreads();
    }
    if (t == 0) g_bsum[b] = sh[0];
}

__global__ void __launch_bounds__(256) k_scan2() {
    __shared__ int sh[256];
    int t = threadIdx.x;
    int v = (t < SCAN_NB) ? g_bsum[t] : 0;
    sh[t] = v;
    __syncthreads();
    for (int off = 1; off < 256; off <<= 1) {
        int u = (t >= off) ? sh[t - off] : 0;
        __syncthreads();
        sh[t] += u;
        __syncthreads();
    }
    if (t < SCAN_NB) g_bsum[t] = sh[t] - v;
    if (t == 255) g_off[N_NODES] = sh[255];
}

__global__ void __launch_bounds__(512) k_scan3() {
    __shared__ int sh[512];
    int b = blockIdx.x, t = threadIdx.x;
    int i = b * 512 + t;
    int v = (i < N_NODES) ? g_off[i] : 0;
    sh[t] = v;
    __syncthreads();
    for (int off = 1; off < 512; off <<= 1) {
        int u = (t >= off) ? sh[t - off] : 0;
        __syncthreads();
        sh[t] += u;
        __syncthreads();
    }
    int excl = sh[t] - v + g_bsum[b];
    if (i < N_NODES) { g_off[i] = excl; g_cursor[i] = excl; }
}

__global__ void k_fill(const unsigned* __restrict__ ei32) {
    int e = blockIdx.x * blockDim.x + threadIdx.x;
    if (e < N_EDGES) {
        int mode = dmode();
        unsigned d = (unsigned)ld_idx(ei32, N_EDGES + e, mode);
        unsigned s = (unsigned)ld_idx(ei32, e, mode);
        if (d < N_NODES && s < N_NODES) {
            int p = atomicAdd(&g_cursor[d], 1);
            g_esrc[p] = (int)s;
        }
    }
}

// x -> linear fp16x2
__global__ void k_cvt_x(const float* __restrict__ x) {
    int idx = blockIdx.x * blockDim.x + threadIdx.x;
    if (idx >= N_NODES * (IN_DIM / 2)) return;
    float2 v = *(const float2*)(x + 2 * (size_t)idx);
    g_x16[idx] = pk_hf2(v.x, v.y);
}

// agg over fp16x2 linear input: acc = in[n] + sum in[src]; emit fp16 A-frag to slot 0.
// Each thread: one node x one 16B chunk (8 cols).
template<int DIM>
__global__ void k_agg16(int insel) {
    const uint32_t* in = insel ? g_h16 : g_x16;
    const int C = DIM / 8;                 // 16B chunks per row
    const int W = DIM / 2;                 // row stride in words
    int idx = blockIdx.x * blockDim.x + threadIdx.x;
    if (idx >= N_NODES * C) return;
    int node = idx / C;
    int c    = idx - node * C;

    uint4 v = *(const uint4*)(in + (size_t)node * W + c * 4);
    float2 f0 = up2(v.x), f1 = up2(v.y), f2 = up2(v.z), f3 = up2(v.w);
    int s = g_off[node], e = g_off[node + 1];
    for (int i = s; i < e; i++) {
        uint4 u = *(const uint4*)(in + (size_t)g_esrc[i] * W + c * 4);
        float2 a = up2(u.x), b = up2(u.y), cc = up2(u.z), dd = up2(u.w);
        f0.x += a.x;  f0.y += a.y;
        f1.x += b.x;  f1.y += b.y;
        f2.x += cc.x; f2.y += cc.y;
        f3.x += dd.x; f3.y += dd.y;
    }
    uint4 o;
    o.x = pk_hf2(f0.x, f0.y);
    o.y = pk_hf2(f1.x, f1.y);
    o.z = pk_hf2(f2.x, f2.y);
    o.w = pk_hf2(f3.x, f3.y);
    int kt  = c >> 1;
    int jj0 = (c & 1) * 4;
    *(uint4*)(g_AH0 + ((size_t)kt * N_PAD2 + node) * 8 + jj0) = o;
}

// prep: pack W[K][128] into fp16x2 B-fragment layout, hi/lo split.
__global__ void k_prepw(const float* __restrict__ W, int K) {
    int idx = blockIdx.x * blockDim.x + threadIdx.x;
    if (idx >= (K / 16) * HIDDEN * 8) return;
    int jj = idx & 7;
    int n  = (idx >> 3) & 127;
    int kt = idx >> 10;
    float w0 = W[(kt * 16 + 2 * jj) * HIDDEN + n];
    float w1 = W[(kt * 16 + 2 * jj + 1) * HIDDEN + n];
    uint32_t h = pk_hf2(w0, w1);
    uint32_t l = pk_hf2(w0 - hf_lo(h), w1 - hf_hi(h));
    g_WpH[idx] = h;
    g_WpL[idx] = l;
}

// ---------------- pipelined tensor-core GEMM (fp16 split, 2 passes) ------
// 128x128 tile, 256 threads. 16-k chunks, cp.async double buffer (2x12KB smem).
// out_mode 0: fp32->g_bufC; 1: fp16 frag->slot1; 2: fp16x2 linear->g_h16.
__global__ void __launch_bounds__(256) k_gemm_mma(int in_slot, const float* __restrict__ bias,
                                                  int out_mode, int K) {
    __shared__ __align__(16) uint32_t smem[6144];   // 2 stages x 3072 words (12KB)
    const uint32_t* AH = afH(in_slot);
    int tid  = threadIdx.x;
    int lane = tid & 31, wid = tid >> 5;
    int row0  = blockIdx.x * 128;
    int rbase = (wid & 3) * 32;
    int nbase = (wid >> 2) * 64;
    int g = lane >> 2, j = lane & 3;
    uint32_t sb = smem_u32(smem);

    float acc[2][8][4];
    #pragma unroll
    for (int mf = 0; mf < 2; mf++)
        #pragma unroll
        for (int nf = 0; nf < 8; nf++)
            #pragma unroll
            for (int c = 0; c < 4; c++) acc[mf][nf][c] = 0.f;

    int nch = K >> 4;
    {
        size_t aoff = ((size_t)0 * N_PAD2 + row0) * 8 + tid * 4;
        CP16(sb + tid * 16,        AH + aoff);
        CP16(sb + 4096 + tid * 16, g_WpH + tid * 4);
        CP16(sb + 8192 + tid * 16, g_WpL + tid * 4);
        CP_COMMIT();
    }
    for (int ch = 0; ch < nch; ch++) {
        if (ch + 1 < nch) {
            uint32_t dst = sb + ((ch + 1) & 1) * 12288;
            size_t aoff = ((size_t)(ch + 1) * N_PAD2 + row0) * 8 + tid * 4;
            size_t boff = (size_t)(ch + 1) * 1024 + tid * 4;
            CP16(dst + tid * 16,        AH + aoff);
            CP16(dst + 4096 + tid * 16, g_WpH + boff);
            CP16(dst + 8192 + tid * 16, g_WpL + boff);
            CP_COMMIT();
            CP_WAIT1();
        } else {
            CP_WAIT0();
        }
        __syncthreads();
        const uint32_t* S   = smem + (ch & 1) * 3072;
        const uint32_t* sAH = S;
        const uint32_t* sBH = S + 1024;
        const uint32_t* sBL = S + 2048;

        uint32_t ah[2][4];
        #pragma unroll
        for (int mf = 0; mf < 2; mf++) {
            int base = (rbase + mf * 16 + g) * 8;
            ah[mf][0] = sAH[base + j];
            ah[mf][1] = sAH[base + 64 + j];
            ah[mf][2] = sAH[base + j + 4];
            ah[mf][3] = sAH[base + 64 + j + 4];
        }
        #pragma unroll
        for (int nf = 0; nf < 8; nf++) {
            int bbase = (nbase + nf * 8 + g) * 8;
            uint32_t b0h = sBH[bbase + j], b1h = sBH[bbase + j + 4];
            uint32_t b0l = sBL[bbase + j], b1l = sBL[bbase + j + 4];
            #pragma unroll
            for (int mf = 0; mf < 2; mf++) {
                MMA16(acc[mf][nf], ah[mf], b0h, b1h);   // hi*hi
                MMA16(acc[mf][nf], ah[mf], b0l, b1l);   // hi*lo
            }
        }
        __syncthreads();
    }

    // epilogue: bias + relu
    #pragma unroll
    for (int mf = 0; mf < 2; mf++) {
        int row = row0 + rbase + mf * 16 + g;
        #pragma unroll
        for (int nf = 0; nf < 8; nf++) {
            int col = nbase + nf * 8 + j * 2;
            float2 bv = *(const float2*)(bias + col);
            float2 o0, o1;
            o0.x = fmaxf(acc[mf][nf][0] + bv.x, 0.f);
            o0.y = fmaxf(acc[mf][nf][1] + bv.y, 0.f);
            o1.x = fmaxf(acc[mf][nf][2] + bv.x, 0.f);
            o1.y = fmaxf(acc[mf][nf][3] + bv.y, 0.f);
            if (out_mode == 0) {
                *(float2*)(g_bufC + (size_t)row * HIDDEN + col)       = o0;
                *(float2*)(g_bufC + (size_t)(row + 8) * HIDDEN + col) = o1;
            } else if (out_mode == 1) {
                int kt = col >> 4, jj = (col & 15) >> 1;
                size_t oa = ((size_t)kt * N_PAD2 + row) * 8 + jj;
                size_t ob = ((size_t)kt * N_PAD2 + row + 8) * 8 + jj;
                g_AH1[oa] = pk_hf2(o0.x, o0.y);
                g_AH1[ob] = pk_hf2(o1.x, o1.y);
            } else {
                g_h16[(size_t)row * (HIDDEN / 2) + (col >> 1)]       = pk_hf2(o0.x, o0.y);
                g_h16[(size_t)(row + 8) * (HIDDEN / 2) + (col >> 1)] = pk_hf2(o1.x, o1.y);
            }
        }
    }
}

__global__ void k_ranges(const unsigned* __restrict__ b32) {
    int g = blockIdx.x * blockDim.x + threadIdx.x;
    if (g > N_GRAPHS) return;
    int mode = dmode();
    int lo = 0, hi = N_NODES;
    while (lo < hi) {
        int mid = (lo + hi) >> 1;
        int bv = ld_idx(b32, mid, mode);
        if (bv < g) lo = mid + 1; else hi = mid;
    }
    g_start[g] = lo;
}

__global__ void __launch_bounds__(128) k_pool(const float* __restrict__ Wc,
                                              const float* __restrict__ bc,
                                              float* __restrict__ out) {
    int g = blockIdx.x;
    int d = threadIdx.x;
    int s = g_start[g], e = g_start[g + 1];
    float acc = 0.f;
    for (int n = s; n < e; n++) acc += g_bufC[(size_t)n * HIDDEN + d];
    float cnt  = (float)(e - s);
    float mean = acc / fmaxf(cnt, 1.0f);
    float v = mean * Wc[d];

    __shared__ float red[128];
    red[d] = v;
    __syncthreads();
    #pragma unroll
    for (int off = 64; off > 0; off >>= 1) {
        if (d < off) red[d] += red[d + off];
        __syncthreads();
    }
    if (d == 0) out[g] = red[0] + bc[0];
}

// staged diagnostic: overwrites out ONLY on failure. m = CSR + 2*bufC
__global__ void __launch_bounds__(256) k_diag(float* __restrict__ out) {
    __shared__ float red[256];
    __shared__ int ok[2];
    int tid = threadIdx.x;
    if (tid == 0) ok[0] = (g_off[N_NODES] == N_EDGES) ? 1 : 0;

    float s = 0.f;
    for (int i = tid; i < 100000; i += 256) s += fabsf(g_bufC[i]);
    red[tid] = s;
    __syncthreads();
    for (int o = 128; o > 0; o >>= 1) {
        if (tid < o) red[tid] += red[tid + o];
        __syncthreads();
    }
    if (tid == 0) { float t = red[0]; ok[1] = (isfinite(t) && t > 0.f) ? 1 : 0; }
    __syncthreads();

    int m = ok[0] + 2 * ok[1];
    if (m == 3) return;
    float V = exp10f((float)(4 + 4 * m));
    for (int g = tid; g < N_GRAPHS; g += 256) out[g] = V;
}

__global__ void k_mark(float* out, float v) {
    int g = blockIdx.x * blockDim.x + threadIdx.x;
    if (g < N_GRAPHS) out[g] = v;
}

// ---------------- launch ----------------
extern "C" void kernel_launch(void* const* d_in, const int* in_sizes, int n_in,
                              void* d_out, int out_size) {
    const float *x, *W1a, *b1a, *W1b, *b1b, *W2a, *b2a, *W2b, *b2b, *Wc, *bc;
    const unsigned *ei, *batch;
    float* out = (float*)d_out;

    if (in_sizes[0] == N_NODES * IN_DIM) {
        x     = (const float*)d_in[0];
        ei    = (const unsigned*)d_in[1];
        batch = (const unsigned*)d_in[2];
        W1a   = (const float*)d_in[3];   b1a = (const float*)d_in[4];
        W1b   = (const float*)d_in[5];   b1b = (const float*)d_in[6];
        W2a   = (const float*)d_in[7];   b2a = (const float*)d_in[8];
        W2b   = (const float*)d_in[9];   b2b = (const float*)d_in[10];
        Wc    = (const float*)d_in[11];  bc  = (const float*)d_in[12];
    } else {
        k_mark<<<2, 256>>>(out, __builtin_nanf(""));
        return;
    }

    // CSR build
    k_zero_counts<<<(N_NODES + 256) / 256, 256>>>();
    k_detect<<<N_EDGES / 256, 256>>>(ei);
    k_count<<<N_EDGES / 256, 256>>>(ei);
    k_scan1<<<SCAN_NB, 512>>>();
    k_scan2<<<1, 256>>>();
    k_scan3<<<SCAN_NB, 512>>>();
    k_fill<<<N_EDGES / 256, 256>>>(ei);

    // conv1: x->fp16; agg -> slot0; GEMM1 -> slot1 (frag); GEMM2 -> g_h16 (linear fp16)
    k_cvt_x<<<(N_NODES * (IN_DIM / 2) + 255) / 256, 256>>>(x);
    k_agg16<IN_DIM><<<(N_NODES * (IN_DIM / 8) + 255) / 256, 256>>>(0);
    k_prepw<<<(IN_DIM / 16) * HIDDEN * 8 / 256, 256>>>(W1a, IN_DIM);
    k_gemm_mma<<<N_TILES, 256>>>(0, b1a, 1, IN_DIM);
    k_prepw<<<(HIDDEN / 16) * HIDDEN * 8 / 256, 256>>>(W1b, HIDDEN);
    k_gemm_mma<<<N_TILES, 256>>>(1, b1b, 2, HIDDEN);

    // conv2: agg(g_h16) -> slot0; GEMM3 -> slot1; GEMM4 -> g_bufC (fp32)
    k_agg16<HIDDEN><<<(N_NODES * (HIDDEN / 8) + 255) / 256, 256>>>(1);
    k_prepw<<<(HIDDEN / 16) * HIDDEN * 8 / 256, 256>>>(W2a, HIDDEN);
    k_gemm_mma<<<N_TILES, 256>>>(0, b2a, 1, HIDDEN);
    k_prepw<<<(HIDDEN / 16) * HIDDEN * 8 / 256, 256>>>(W2b, HIDDEN);
    k_gemm_mma<<<N_TILES, 256>>>(1, b2b, 0, HIDDEN);

    // pool + head
    k_ranges<<<3, 256>>>(batch);
    k_pool<<<N_GRAPHS, 128>>>(Wc, bc, out);

    // diagnostic override only on failure
    k_diag<<<1, 256>>>(out);
}